// round 8
// baseline (speedup 1.0000x reference)
#include <cuda_runtime.h>
#include <cuda_fp16.h>

// Problem dims
#define NN    128            // H == W == kernel_size
#define NH    65             // half-spectrum width (N/2+1)
#define NHP   68             // padded row stride for Yc
#define NB    32             // batch
#define NC    64             // in channels
#define NO    64             // out channels
#define NBC   (NB*NC)        // 2048
#define NBO   (NB*NO)        // 2048
#define NFREQ (NH*NN)        // 8320, f = wp*128 + h
#define LDF   129            // smem FFT row stride
#define KWT   13             // kw tile width (5*13 = 65 = NH exactly)

// ---------------- scratch (device globals; allocation-free rule) ----------------
__device__ __half2 g_X1h[(size_t)NBC * NH * NN];    // [b*c][wp][h]   fp16 (r,i)
__device__ __half2 g_Xfh[(size_t)NFREQ * NB * NC];  // [f][b][c]      fp16 (r,i)
__device__ __half2 g_Wf[(size_t)NFREQ * NC * NO];   // [f][c][o]      fp16 (r,i)
__device__ __half2 g_Yfh[(size_t)NFREQ * NB * NO];  // [f][b][o]      fp16 (r,i)
__device__ __half2 g_Ych[(size_t)NBO * NN * NHP];   // [bo][h][wp]    fp16 (r,i)

// ---------------- packed f32x2 helpers (FFMA2) ----------------
__device__ __forceinline__ unsigned long long pk2(float x, float y) {
    unsigned long long r;
    asm("mov.b64 %0, {%1, %2};" : "=l"(r) : "f"(x), "f"(y));
    return r;
}
__device__ __forceinline__ void ffma2(unsigned long long& d, unsigned long long a, unsigned long long b) {
    asm("fma.rn.f32x2 %0, %1, %2, %0;" : "+l"(d) : "l"(a), "l"(b));
}
__device__ __forceinline__ float2 unpk2(unsigned long long v) {
    float2 f;
    asm("mov.b64 {%0, %1}, %2;" : "=f"(f.x), "=f"(f.y) : "l"(v));
    return f;
}
__device__ __forceinline__ unsigned h2u(__half2 h) { return *(unsigned*)&h; }

// ---------------- FFT helpers ----------------
__device__ __forceinline__ void init_tw(float2* tw) {
    int tid = threadIdx.x;
    if (tid < 64) {
        float s, c;
        sincospif(-(float)tid * (1.0f / 64.0f), &s, &c);
        tw[tid] = make_float2(c, s);
    }
}

__device__ __forceinline__ float2 f2add(float2 a, float2 b) { return make_float2(a.x + b.x, a.y + b.y); }
__device__ __forceinline__ float2 f2sub(float2 a, float2 b) { return make_float2(a.x - b.x, a.y - b.y); }

template <int SIGN>
__device__ __forceinline__ float2 cmul_tw(float2 w, float2 z) {
    float wy = (SIGN < 0) ? w.y : -w.y;
    return make_float2(z.x * w.x - z.y * wy, z.x * wy + z.y * w.x);
}

#define SWZI(p) ((p) ^ ((((unsigned)(p)) >> 4) & 7))

// Fused 3x radix-2 (= radix-8) Stockham group. 16 threads per FFT.
template <int SIGN, int S, bool SWZ_ST, bool SWZ_LD>
__device__ __forceinline__ void radix8_group(const float2* src, float2* dst, const float2* tw) {
    int tid = threadIdx.x;
    int fi = tid >> 4;
    int i  = tid & 15;
    const int tk = i & ~(S - 1);
    const float2* Sr = src + fi * LDF;
    float2* Dr = dst + fi * LDF;

    float2 a[8];
#pragma unroll
    for (int k = 0; k < 8; k++) {
        int p = i + 16 * k;
        if (SWZ_LD) p = SWZI(p);
        a[k] = Sr[p];
    }
    float2 v[4], u[4];
#pragma unroll
    for (int k = 0; k < 4; k++) {
        v[k] = f2add(a[k], a[k + 4]);
        u[k] = cmul_tw<SIGN>(tw[tk + 16 * k], f2sub(a[k], a[k + 4]));
    }
    float2 w0 = tw[2 * tk], w1 = tw[2 * tk + 32];
    float2 g[4], h[4];
    g[0] = f2add(v[0], v[2]);  g[2] = cmul_tw<SIGN>(w0, f2sub(v[0], v[2]));
    g[1] = f2add(u[0], u[2]);  g[3] = cmul_tw<SIGN>(w0, f2sub(u[0], u[2]));
    h[0] = f2add(v[1], v[3]);  h[2] = cmul_tw<SIGN>(w1, f2sub(v[1], v[3]));
    h[1] = f2add(u[1], u[3]);  h[3] = cmul_tw<SIGN>(w1, f2sub(u[1], u[3]));
    float2 w2 = tw[4 * tk];
    float2 e[8];
#pragma unroll
    for (int k = 0; k < 4; k++) {
        e[k]     = f2add(g[k], h[k]);
        e[k + 4] = cmul_tw<SIGN>(w2, f2sub(g[k], h[k]));
    }
    const int Q = i + 7 * tk;
#pragma unroll
    for (int k = 0; k < 8; k++) {
        int p = Q + k * S;
        if (SWZ_ST) p = SWZI(p);
        Dr[p] = e[k];
    }
}

// 16 FFTs of length 128 per 256-thread block. Input bufA, result bufB.
template <int SIGN>
__device__ __forceinline__ void fft128_block16(float2* bufA, float2* bufB, const float2* tw) {
    radix8_group<SIGN, 1, true,  false>(bufA, bufB, tw);
    __syncthreads();
    radix8_group<SIGN, 8, false, true >(bufB, bufA, tw);
    __syncthreads();
    int tid = threadIdx.x;
#pragma unroll
    for (int itb = 0; itb < 4; itb++) {
        int it  = tid + itb * 256;
        int f2  = it >> 6;
        int idx = it & 63;
        float2 x = bufA[f2 * LDF + idx];
        float2 y = bufA[f2 * LDF + idx + 64];
        bufB[f2 * LDF + idx]      = f2add(x, y);
        bufB[f2 * LDF + idx + 64] = f2sub(x, y);
    }
    __syncthreads();
}

// ---------------- K1: forward row FFT with real-pair packing, fp16 output.
__global__ void __launch_bounds__(256) k1_rowfft(const float* __restrict__ x) {
    __shared__ float2 bufA[16 * LDF], bufB[16 * LDF];
    __shared__ float2 tw[64];
    init_tw(tw);
    int tid = threadIdx.x;
    int blk = blockIdx.x;
    int bc = blk >> 2;
    int h0 = (blk & 3) << 5;              // 32 rows
    const float* xp = x + (size_t)bc * NN * NN + (size_t)h0 * NN;
    for (int i = tid; i < 16 * NN; i += 256) {
        int p = i >> 7, w = i & 127;
        bufA[p * LDF + w] = make_float2(xp[(2 * p) * NN + w], xp[(2 * p + 1) * NN + w]);
    }
    __syncthreads();
    fft128_block16<-1>(bufA, bufB, tw);
    __half2* out = g_X1h + (size_t)bc * NH * NN;
    for (int i = tid; i < NH * 16; i += 256) {
        int p = i & 15, wp = i >> 4;
        float2 A = bufB[p * LDF + wp];
        float2 B = bufB[p * LDF + ((NN - wp) & 127)];
        __half2 X0 = __floats2half2_rn(0.5f * (A.x + B.x), 0.5f * (A.y - B.y));
        __half2 X1 = __floats2half2_rn(0.5f * (A.y + B.y), 0.5f * (B.x - A.x));
        *(uint2*)&out[(size_t)wp * NN + h0 + 2 * p] = make_uint2(h2u(X0), h2u(X1));
    }
}

// ---------------- K2: forward column FFT, scatter to freq-major [f][b][c], fp16 out
__global__ void __launch_bounds__(256) k2_colfft() {
    __shared__ float2 bufA[16 * LDF], bufB[16 * LDF];
    __shared__ float2 tw[64];
    init_tw(tw);
    int tid = threadIdx.x;
    int blk = blockIdx.x;
    int b   = blk / (NH * 4);
    int rem = blk % (NH * 4);
    int wp  = rem >> 2;
    int c0  = (rem & 3) << 4;
    for (int i = tid; i < 16 * NN; i += 256) {
        int h = i & 127, cl = i >> 7;
        bufA[cl * LDF + h] = __half22float2(
            g_X1h[((size_t)(b * NC + c0 + cl) * NH + wp) * NN + h]);
    }
    __syncthreads();
    fft128_block16<-1>(bufA, bufB, tw);
    for (int i = tid; i < 16 * NN; i += 256) {
        int cl = i & 15, h = i >> 4;
        float2 v = bufB[cl * LDF + h];
        g_Xfh[((size_t)(wp * NN + h)) * NBC + b * NC + c0 + cl] =
            __floats2half2_rn(v.x, v.y);
    }
}

// ---------------- KW: Weff[f][c][o] = 0.5*(W[k] + conj(W[-k])), fp16 output.
__global__ void __launch_bounds__(256) kw_weff(const float* __restrict__ wr,
                                               const float* __restrict__ wi) {
    __shared__ __half2 S[64][KWT + 3];
    int tid = threadIdx.x;
    int blk = blockIdx.x;                 // c*(128*5) + h*5 + wt
    int c   = blk / (NN * 5);
    int rem = blk % (NN * 5);
    int h   = rem / 5;
    int wt  = rem % 5;
    int wp0 = wt * KWT;
    int h2  = (NN - h) & 127;
    for (int i = tid; i < 64 * 16; i += 256) {
        int wl = i & 15, o = i >> 4;
        if (wl < KWT) {
            int wp = wp0 + wl;            // < 65
            int w2 = (NN - wp) & 127;
            size_t base = (size_t)(o * NC + c) * (NN * NN);
            float a1 = wr[base + (size_t)h  * NN + wp];
            float b1 = wi[base + (size_t)h  * NN + wp];
            float a2 = wr[base + (size_t)h2 * NN + w2];
            float b2 = wi[base + (size_t)h2 * NN + w2];
            S[o][wl] = __floats2half2_rn(0.5f * (a1 + a2), 0.5f * (b1 - b2));
        }
    }
    __syncthreads();
    for (int i = tid; i < 64 * 16; i += 256) {
        int o = i & 63, wl = i >> 6;
        if (wl < KWT) {
            int wp = wp0 + wl;
            g_Wf[((size_t)(wp * NN + h)) * (NC * NO) + c * NO + o] = S[o][wl];
        }
    }
}

// ---------------- K3: per-frequency complex GEMM  Y[b][o] = sum_c X[b][c] * Weff[c][o]
// 128 threads; 2 outputs x 8 batches per thread. W interleaved fp16 in smem
// (one LDS.64 per c-iter); X fp32 planes. ~34KB -> 6 blocks/SM.
__global__ void __launch_bounds__(128, 6) k3_contract() {
    __shared__ __align__(16) float Xr_s[NC][NB + 4];    // 9.2 KB
    __shared__ __align__(16) float Xi_s[NC][NB + 4];    // 9.2 KB
    __shared__ __align__(8)  uint2 Wri[NC][NO / 2];     // 16 KB: .x=r-pair, .y=i-pair
    int tid = threadIdx.x;
    int f = blockIdx.x;
    const __half2* __restrict__ Xg = g_Xfh + (size_t)f * (NB * NC);
    const uint4* __restrict__ Wg4 = (const uint4*)(g_Wf + (size_t)f * (NC * NO));
    for (int i = tid; i < NB * NC; i += 128) {
        float2 v = __half22float2(Xg[i]);
        int b = i >> 6, c = i & 63;
        Xr_s[c][b] = v.x;
        Xi_s[c][b] = v.y;
    }
    for (int i = tid; i < (NC * NO) / 4; i += 128) {   // uint4 = 4 half2 = 4 o's
        uint4 v = Wg4[i];
        int base = i * 4;
        int c = base >> 6, o = base & 63;
        __half2 p0 = *(__half2*)&v.x, p1 = *(__half2*)&v.y;
        __half2 p2 = *(__half2*)&v.z, p3 = *(__half2*)&v.w;
        Wri[c][(o >> 1)]     = make_uint2(h2u(__lows2half2(p0, p1)), h2u(__highs2half2(p0, p1)));
        Wri[c][(o >> 1) + 1] = make_uint2(h2u(__lows2half2(p2, p3)), h2u(__highs2half2(p2, p3)));
    }
    __syncthreads();

    int b0 = (tid & 3) << 3;              // 8 batches per thread
    int op = tid >> 2;                    // o-pair index; o0 = 2*op
    unsigned long long ar[2][4], ai[2][4];
#pragma unroll
    for (int o = 0; o < 2; o++)
#pragma unroll
        for (int k = 0; k < 4; k++) { ar[o][k] = 0ull; ai[o][k] = 0ull; }

#pragma unroll 4
    for (int c = 0; c < NC; c++) {
        ulonglong2 xrA = *(const ulonglong2*)&Xr_s[c][b0];
        ulonglong2 xrB = *(const ulonglong2*)&Xr_s[c][b0 + 4];
        ulonglong2 xiA = *(const ulonglong2*)&Xi_s[c][b0];
        ulonglong2 xiB = *(const ulonglong2*)&Xi_s[c][b0 + 4];
        uint2 wv = Wri[c][op];
        float2 wrv = __half22float2(*(__half2*)&wv.x);
        float2 wiv = __half22float2(*(__half2*)&wv.y);
        unsigned long long xrp[4] = { xrA.x, xrA.y, xrB.x, xrB.y };
        unsigned long long xip[4] = { xiA.x, xiA.y, xiB.x, xiB.y };
#pragma unroll
        for (int o = 0; o < 2; o++) {
            float wrs = o ? wrv.y : wrv.x;
            float wis = o ? wiv.y : wiv.x;
            unsigned long long wrd = pk2(wrs, wrs);
            unsigned long long wid = pk2(wis, wis);
            unsigned long long wnd = pk2(-wis, -wis);
#pragma unroll
            for (int k = 0; k < 4; k++) {
                ffma2(ar[o][k], xrp[k], wrd);   // ar += xr*wr
                ffma2(ar[o][k], xip[k], wnd);   // ar -= xi*wi
                ffma2(ai[o][k], xrp[k], wid);   // ai += xr*wi
                ffma2(ai[o][k], xip[k], wrd);   // ai += xi*wr
            }
        }
    }
    __half2* Ygh = g_Yfh + (size_t)f * (NB * NO);
    int o0 = op << 1;
#pragma unroll
    for (int k = 0; k < 4; k++) {
        float2 a0r = unpk2(ar[0][k]);
        float2 a0i = unpk2(ai[0][k]);
        float2 a1r = unpk2(ar[1][k]);
        float2 a1i = unpk2(ai[1][k]);
        __half2 e00 = __floats2half2_rn(a0r.x, a0i.x);
        __half2 e01 = __floats2half2_rn(a1r.x, a1i.x);
        __half2 e10 = __floats2half2_rn(a0r.y, a0i.y);
        __half2 e11 = __floats2half2_rn(a1r.y, a1i.y);
        *(uint2*)&Ygh[(b0 + 2 * k) * NO + o0]     = make_uint2(h2u(e00), h2u(e01));
        *(uint2*)&Ygh[(b0 + 2 * k + 1) * NO + o0] = make_uint2(h2u(e10), h2u(e11));
    }
}

// ---------------- K4: inverse column FFT (along h), to [bo][h][wp] fp16 (padded)
__global__ void __launch_bounds__(256) k4_colifft() {
    __shared__ float2 bufA[16 * LDF], bufB[16 * LDF];
    __shared__ float2 tw[64];
    init_tw(tw);
    int tid = threadIdx.x;
    int blk = blockIdx.x;
    int bt = blk / 17;
    int wt = blk % 17;
    int bo0 = bt << 2;
    int wp0 = wt << 2;
    for (int i = tid; i < 4 * NN; i += 256) {          // 512 uint4 loads (4 bo each)
        int wl = i & 3, h = i >> 2;
        int wp = wp0 + wl;
        uint4 v = make_uint4(0u, 0u, 0u, 0u);
        if (wp < NH)
            v = *(const uint4*)&g_Yfh[((size_t)(wp * NN + h)) * NBO + bo0];
        const unsigned* vp = &v.x;
#pragma unroll
        for (int bl = 0; bl < 4; bl++) {
            __half2 hv = *(__half2*)&vp[bl];
            bufA[((wl << 2) + bl) * LDF + h] = __half22float2(hv);
        }
    }
    __syncthreads();
    fft128_block16<1>(bufA, bufB, tw);
    for (int i = tid; i < 16 * NN; i += 256) {
        int wl = i & 3, bl = (i >> 2) & 3, h = i >> 4;
        int wp = wp0 + wl;
        int fi = (wl << 2) + bl;
        if (wp < NH) {
            float2 v = bufB[fi * LDF + h];
            g_Ych[((size_t)(bo0 + bl) * NN + h) * NHP + wp] = __floats2half2_rn(v.x, v.y);
        }
    }
}

// ---------------- K5: inverse row FFT with real-pair packing + bias + relu
__global__ void __launch_bounds__(256) k5_rowifft(const float* __restrict__ bias,
                                                  float* __restrict__ out) {
    __shared__ float2 bufA[16 * LDF], bufB[16 * LDF];
    __shared__ float2 tw[64];
    init_tw(tw);
    int tid = threadIdx.x;
    int blk = blockIdx.x;
    int bo = blk >> 2;
    int h0 = (blk & 3) << 5;              // 32 rows = 16 pairs
    int o  = bo & 63;
    const __half2* Yrow = g_Ych + (size_t)bo * NN * NHP;
    for (int i = tid; i < 16 * NN; i += 256) {
        int p = i >> 7, w = i & 127;
        int wp = (w <= 64) ? w : (NN - w);
        float2 A0 = __half22float2(Yrow[(size_t)(h0 + 2 * p)     * NHP + wp]);
        float2 A1 = __half22float2(Yrow[(size_t)(h0 + 2 * p + 1) * NHP + wp]);
        if (w > 64) { A0.y = -A0.y; A1.y = -A1.y; }
        bufA[p * LDF + w] = make_float2(A0.x - A1.y, A0.y + A1.x);
    }
    __syncthreads();
    fft128_block16<1>(bufA, bufB, tw);
    float bv = bias[o];
    const float scale = 1.0f / 16384.0f;
    float* op = out + (size_t)bo * NN * NN;
    for (int i = tid; i < 16 * NN; i += 256) {
        int p = i >> 7, w = i & 127;
        float2 v = bufB[p * LDF + w];
        float v0 = v.x * scale + bv;
        float v1 = v.y * scale + bv;
        op[(size_t)(h0 + 2 * p)     * NN + w] = fmaxf(v0, 0.f);
        op[(size_t)(h0 + 2 * p + 1) * NN + w] = fmaxf(v1, 0.f);
    }
}

// ---------------- launch ----------------
extern "C" void kernel_launch(void* const* d_in, const int* in_sizes, int n_in,
                              void* d_out, int out_size) {
    const float* x    = (const float*)d_in[0];
    const float* wr   = (const float*)d_in[1];
    const float* wi   = (const float*)d_in[2];
    const float* bias = (const float*)d_in[3];
    float* out = (float*)d_out;

    k1_rowfft <<<NBC * 4, 256>>>(x);             // 8192 blocks
    kw_weff   <<<NC * NN * 5, 256>>>(wr, wi);    // 40960 blocks
    k2_colfft <<<NB * NH * 4, 256>>>();          // 8320 blocks
    k3_contract<<<NFREQ, 128>>>();               // 8320 blocks
    k4_colifft<<<(NBO / 4) * 17, 256>>>();       // 8704 blocks
    k5_rowifft<<<NBO * 4, 256>>>(bias, out);     // 8192 blocks
}

// round 10
// speedup vs baseline: 1.2211x; 1.2211x over previous
#include <cuda_runtime.h>
#include <cuda_fp16.h>

// Problem dims
#define NN    128            // H == W == kernel_size
#define NH    65             // half-spectrum width (N/2+1)
#define NHP   68             // padded row stride for Yc
#define NB    32             // batch
#define NC    64             // in channels
#define NO    64             // out channels
#define NBC   (NB*NC)        // 2048
#define NBO   (NB*NO)        // 2048
#define NFREQ (NH*NN)        // 8320, f = wp*128 + h
#define LDF   129            // smem FFT row stride
#define KWT   13             // kw tile width (5*13 = 65 = NH exactly)

// ---------------- scratch (device globals; allocation-free rule) ----------------
__device__ __half2 g_X1h[(size_t)NBC * NH * NN];    // [b*c][wp][h]   fp16 (r,i)
__device__ __half2 g_Xfh[(size_t)NFREQ * NB * NC];  // [f][b][c]      fp16 (r,i)
__device__ __half2 g_Wf[(size_t)NFREQ * NC * NO];   // [f][c][o]      fp16 (r,i)
__device__ __half2 g_Yfh[(size_t)NFREQ * NB * NO];  // [f][b][o]      fp16 (r,i)
__device__ __half2 g_Ych[(size_t)NBO * NN * NHP];   // [bo][h][wp]    fp16 (r,i)

__device__ __forceinline__ unsigned h2u(__half2 h) { return *(unsigned*)&h; }

// ---------------- FFT helpers ----------------
__device__ __forceinline__ void init_tw(float2* tw) {
    int tid = threadIdx.x;
    if (tid < 64) {
        float s, c;
        sincospif(-(float)tid * (1.0f / 64.0f), &s, &c);
        tw[tid] = make_float2(c, s);
    }
}

__device__ __forceinline__ float2 f2add(float2 a, float2 b) { return make_float2(a.x + b.x, a.y + b.y); }
__device__ __forceinline__ float2 f2sub(float2 a, float2 b) { return make_float2(a.x - b.x, a.y - b.y); }

template <int SIGN>
__device__ __forceinline__ float2 cmul_tw(float2 w, float2 z) {
    float wy = (SIGN < 0) ? w.y : -w.y;
    return make_float2(z.x * w.x - z.y * wy, z.x * wy + z.y * w.x);
}

#define SWZI(p) ((p) ^ ((((unsigned)(p)) >> 4) & 7))

// Fused 3x radix-2 (= radix-8) Stockham group. 16 threads per FFT.
template <int SIGN, int S, bool SWZ_ST, bool SWZ_LD>
__device__ __forceinline__ void radix8_group(const float2* src, float2* dst, const float2* tw) {
    int tid = threadIdx.x;
    int fi = tid >> 4;
    int i  = tid & 15;
    const int tk = i & ~(S - 1);
    const float2* Sr = src + fi * LDF;
    float2* Dr = dst + fi * LDF;

    float2 a[8];
#pragma unroll
    for (int k = 0; k < 8; k++) {
        int p = i + 16 * k;
        if (SWZ_LD) p = SWZI(p);
        a[k] = Sr[p];
    }
    float2 v[4], u[4];
#pragma unroll
    for (int k = 0; k < 4; k++) {
        v[k] = f2add(a[k], a[k + 4]);
        u[k] = cmul_tw<SIGN>(tw[tk + 16 * k], f2sub(a[k], a[k + 4]));
    }
    float2 w0 = tw[2 * tk], w1 = tw[2 * tk + 32];
    float2 g[4], h[4];
    g[0] = f2add(v[0], v[2]);  g[2] = cmul_tw<SIGN>(w0, f2sub(v[0], v[2]));
    g[1] = f2add(u[0], u[2]);  g[3] = cmul_tw<SIGN>(w0, f2sub(u[0], u[2]));
    h[0] = f2add(v[1], v[3]);  h[2] = cmul_tw<SIGN>(w1, f2sub(v[1], v[3]));
    h[1] = f2add(u[1], u[3]);  h[3] = cmul_tw<SIGN>(w1, f2sub(u[1], u[3]));
    float2 w2 = tw[4 * tk];
    float2 e[8];
#pragma unroll
    for (int k = 0; k < 4; k++) {
        e[k]     = f2add(g[k], h[k]);
        e[k + 4] = cmul_tw<SIGN>(w2, f2sub(g[k], h[k]));
    }
    const int Q = i + 7 * tk;
#pragma unroll
    for (int k = 0; k < 8; k++) {
        int p = Q + k * S;
        if (SWZ_ST) p = SWZI(p);
        Dr[p] = e[k];
    }
}

// 16 FFTs of length 128 per 256-thread block. Input bufA, result bufB.
template <int SIGN>
__device__ __forceinline__ void fft128_block16(float2* bufA, float2* bufB, const float2* tw) {
    radix8_group<SIGN, 1, true,  false>(bufA, bufB, tw);
    __syncthreads();
    radix8_group<SIGN, 8, false, true >(bufB, bufA, tw);
    __syncthreads();
    int tid = threadIdx.x;
#pragma unroll
    for (int itb = 0; itb < 4; itb++) {
        int it  = tid + itb * 256;
        int f2  = it >> 6;
        int idx = it & 63;
        float2 x = bufA[f2 * LDF + idx];
        float2 y = bufA[f2 * LDF + idx + 64];
        bufB[f2 * LDF + idx]      = f2add(x, y);
        bufB[f2 * LDF + idx + 64] = f2sub(x, y);
    }
    __syncthreads();
}

// ---------------- K1: forward row FFT with real-pair packing, fp16 output.
__global__ void __launch_bounds__(256) k1_rowfft(const float* __restrict__ x) {
    __shared__ float2 bufA[16 * LDF], bufB[16 * LDF];
    __shared__ float2 tw[64];
    init_tw(tw);
    int tid = threadIdx.x;
    int blk = blockIdx.x;
    int bc = blk >> 2;
    int h0 = (blk & 3) << 5;              // 32 rows
    const float* xp = x + (size_t)bc * NN * NN + (size_t)h0 * NN;
    for (int i = tid; i < 16 * NN; i += 256) {
        int p = i >> 7, w = i & 127;
        bufA[p * LDF + w] = make_float2(xp[(2 * p) * NN + w], xp[(2 * p + 1) * NN + w]);
    }
    __syncthreads();
    fft128_block16<-1>(bufA, bufB, tw);
    __half2* out = g_X1h + (size_t)bc * NH * NN;
    for (int i = tid; i < NH * 16; i += 256) {
        int p = i & 15, wp = i >> 4;
        float2 A = bufB[p * LDF + wp];
        float2 B = bufB[p * LDF + ((NN - wp) & 127)];
        __half2 X0 = __floats2half2_rn(0.5f * (A.x + B.x), 0.5f * (A.y - B.y));
        __half2 X1 = __floats2half2_rn(0.5f * (A.y + B.y), 0.5f * (B.x - A.x));
        *(uint2*)&out[(size_t)wp * NN + h0 + 2 * p] = make_uint2(h2u(X0), h2u(X1));
    }
}

// ---------------- K2: forward column FFT, scatter to freq-major [f][b][c], fp16 out
__global__ void __launch_bounds__(256) k2_colfft() {
    __shared__ float2 bufA[16 * LDF], bufB[16 * LDF];
    __shared__ float2 tw[64];
    init_tw(tw);
    int tid = threadIdx.x;
    int blk = blockIdx.x;
    int b   = blk / (NH * 4);
    int rem = blk % (NH * 4);
    int wp  = rem >> 2;
    int c0  = (rem & 3) << 4;
    for (int i = tid; i < 16 * NN; i += 256) {
        int h = i & 127, cl = i >> 7;
        bufA[cl * LDF + h] = __half22float2(
            g_X1h[((size_t)(b * NC + c0 + cl) * NH + wp) * NN + h]);
    }
    __syncthreads();
    fft128_block16<-1>(bufA, bufB, tw);
    for (int i = tid; i < 16 * NN; i += 256) {
        int cl = i & 15, h = i >> 4;
        float2 v = bufB[cl * LDF + h];
        g_Xfh[((size_t)(wp * NN + h)) * NBC + b * NC + c0 + cl] =
            __floats2half2_rn(v.x, v.y);
    }
}

// ---------------- KW: Weff[f][c][o] = 0.5*(W[k] + conj(W[-k])), fp16 output.
__global__ void __launch_bounds__(256) kw_weff(const float* __restrict__ wr,
                                               const float* __restrict__ wi) {
    __shared__ __half2 S[64][KWT + 3];
    int tid = threadIdx.x;
    int blk = blockIdx.x;                 // c*(128*5) + h*5 + wt
    int c   = blk / (NN * 5);
    int rem = blk % (NN * 5);
    int h   = rem / 5;
    int wt  = rem % 5;
    int wp0 = wt * KWT;
    int h2  = (NN - h) & 127;
    for (int i = tid; i < 64 * 16; i += 256) {
        int wl = i & 15, o = i >> 4;
        if (wl < KWT) {
            int wp = wp0 + wl;            // < 65
            int w2 = (NN - wp) & 127;
            size_t base = (size_t)(o * NC + c) * (NN * NN);
            float a1 = wr[base + (size_t)h  * NN + wp];
            float b1 = wi[base + (size_t)h  * NN + wp];
            float a2 = wr[base + (size_t)h2 * NN + w2];
            float b2 = wi[base + (size_t)h2 * NN + w2];
            S[o][wl] = __floats2half2_rn(0.5f * (a1 + a2), 0.5f * (b1 - b2));
        }
    }
    __syncthreads();
    for (int i = tid; i < 64 * 16; i += 256) {
        int o = i & 63, wl = i >> 6;
        if (wl < KWT) {
            int wp = wp0 + wl;
            g_Wf[((size_t)(wp * NN + h)) * (NC * NO) + c * NO + o] = S[o][wl];
        }
    }
}

// ---------------- K3: per-frequency complex GEMM via tensor cores.
// Real block embedding: Y[32, 2*NO] = A[32, 2*NC] @ B[2*NC, 2*NO] where
//   A[b][2c]=xr, A[b][2c+1]=xi      (== raw g_Xfh row: half2 (r,i) interleave)
//   B[2c][2o]=wr, B[2c][2o+1]=wi    (== raw g_Wf half2)
//   B[2c+1][2o]=-wi, B[2c+1][2o+1]=wr
// mma.sync m16n8k16 f32.f16.f16.f32: products exact, fp32 accumulate ->
// identical precision to the FFMA2 path. 128 threads = 4 warps; warp w owns
// cols [32w, 32w+32) (4 n-tiles), both 16-row M tiles, full K=128 loop.
#define LDA 136   // A_s row stride (halves): bank = 4*row mod 32, conflict-free
#define LDB 136
__global__ void __launch_bounds__(128) k3_contract() {
    __shared__ __align__(16) __half A_s[32][LDA];    // 8.5 KB
    __shared__ __align__(16) __half B_s[128][LDB];   // 34 KB
    int tid = threadIdx.x;
    int lane = tid & 31, warp = tid >> 5;
    int f = blockIdx.x;

    // A fill: straight copy, 32 rows x 128 halves (16 uint4 per row)
    const uint4* __restrict__ Xg4 = (const uint4*)(g_Xfh + (size_t)f * NBC);
    for (int i = tid; i < 32 * 16; i += 128) {
        int b = i >> 4, q = i & 15;
        *(uint4*)&A_s[b][q * 8] = Xg4[i];
    }
    // B fill: row 2c = verbatim W half2s; row 2c+1 = per-pair (-wi, wr)
    const uint4* __restrict__ Wg4 = (const uint4*)(g_Wf + (size_t)f * (NC * NO));
    for (int i = tid; i < 1024; i += 128) {
        int c = i >> 4, og = i & 15;       // og: group of 4 o's
        uint4 v = Wg4[i];
        *(uint4*)&B_s[2 * c][8 * og] = v;
        __half2* hv = (__half2*)&v;
        uint4 t;
        __half2* ht = (__half2*)&t;
#pragma unroll
        for (int j = 0; j < 4; j++)
            ht[j] = __halves2half2(__hneg(__high2half(hv[j])), __low2half(hv[j]));
        *(uint4*)&B_s[2 * c + 1][8 * og] = t;
    }
    __syncthreads();

    int n0b = warp * 32;
    float acc[2][4][4];
#pragma unroll
    for (int mt = 0; mt < 2; mt++)
#pragma unroll
        for (int nt = 0; nt < 4; nt++)
#pragma unroll
            for (int r = 0; r < 4; r++) acc[mt][nt][r] = 0.f;

#pragma unroll
    for (int k = 0; k < 8; k++) {
        unsigned a[2][4], b[4][2];
#pragma unroll
        for (int mt = 0; mt < 2; mt++) {
            unsigned addr = (unsigned)__cvta_generic_to_shared(
                &A_s[mt * 16 + (lane & 15)][k * 16 + 8 * (lane >> 4)]);
            asm volatile("ldmatrix.sync.aligned.m8n8.x4.shared.b16 {%0,%1,%2,%3}, [%4];"
                : "=r"(a[mt][0]), "=r"(a[mt][1]), "=r"(a[mt][2]), "=r"(a[mt][3])
                : "r"(addr));
        }
#pragma unroll
        for (int nt = 0; nt < 4; nt++) {
            unsigned addr = (unsigned)__cvta_generic_to_shared(
                &B_s[k * 16 + (lane & 15)][n0b + nt * 8]);
            asm volatile("ldmatrix.sync.aligned.m8n8.x2.trans.shared.b16 {%0,%1}, [%2];"
                : "=r"(b[nt][0]), "=r"(b[nt][1])
                : "r"(addr));
        }
#pragma unroll
        for (int mt = 0; mt < 2; mt++)
#pragma unroll
            for (int nt = 0; nt < 4; nt++)
                asm volatile(
                    "mma.sync.aligned.m16n8k16.row.col.f32.f16.f16.f32 "
                    "{%0,%1,%2,%3}, {%4,%5,%6,%7}, {%8,%9}, {%0,%1,%2,%3};"
                    : "+f"(acc[mt][nt][0]), "+f"(acc[mt][nt][1]),
                      "+f"(acc[mt][nt][2]), "+f"(acc[mt][nt][3])
                    : "r"(a[mt][0]), "r"(a[mt][1]), "r"(a[mt][2]), "r"(a[mt][3]),
                      "r"(b[nt][0]), "r"(b[nt][1]));
    }

    // Store: acc lane layout m16n8 -> (c0,c1) = row g, cols (2*tig, 2*tig+1)
    // = one (Yr, Yi) half2 at o = n0/2 + nt*4 + tig; (c2,c3) = row g+8.
    __half2* __restrict__ Ygh = g_Yfh + (size_t)f * (NB * NO);
    int g = lane >> 2, tig = lane & 3;
#pragma unroll
    for (int mt = 0; mt < 2; mt++)
#pragma unroll
        for (int nt = 0; nt < 4; nt++) {
            int o  = (n0b >> 1) + (nt << 2) + tig;
            int b0 = mt * 16 + g;
            Ygh[b0 * NO + o]       = __floats2half2_rn(acc[mt][nt][0], acc[mt][nt][1]);
            Ygh[(b0 + 8) * NO + o] = __floats2half2_rn(acc[mt][nt][2], acc[mt][nt][3]);
        }
}

// ---------------- K4: inverse column FFT (along h), to [bo][h][wp] fp16 (padded)
__global__ void __launch_bounds__(256) k4_colifft() {
    __shared__ float2 bufA[16 * LDF], bufB[16 * LDF];
    __shared__ float2 tw[64];
    init_tw(tw);
    int tid = threadIdx.x;
    int blk = blockIdx.x;
    int bt = blk / 17;
    int wt = blk % 17;
    int bo0 = bt << 2;
    int wp0 = wt << 2;
    for (int i = tid; i < 4 * NN; i += 256) {          // 512 uint4 loads (4 bo each)
        int wl = i & 3, h = i >> 2;
        int wp = wp0 + wl;
        uint4 v = make_uint4(0u, 0u, 0u, 0u);
        if (wp < NH)
            v = *(const uint4*)&g_Yfh[((size_t)(wp * NN + h)) * NBO + bo0];
        const unsigned* vp = &v.x;
#pragma unroll
        for (int bl = 0; bl < 4; bl++) {
            __half2 hv = *(__half2*)&vp[bl];
            bufA[((wl << 2) + bl) * LDF + h] = __half22float2(hv);
        }
    }
    __syncthreads();
    fft128_block16<1>(bufA, bufB, tw);
    for (int i = tid; i < 16 * NN; i += 256) {
        int wl = i & 3, bl = (i >> 2) & 3, h = i >> 4;
        int wp = wp0 + wl;
        int fi = (wl << 2) + bl;
        if (wp < NH) {
            float2 v = bufB[fi * LDF + h];
            g_Ych[((size_t)(bo0 + bl) * NN + h) * NHP + wp] = __floats2half2_rn(v.x, v.y);
        }
    }
}

// ---------------- K5: inverse row FFT with real-pair packing + bias + relu
__global__ void __launch_bounds__(256) k5_rowifft(const float* __restrict__ bias,
                                                  float* __restrict__ out) {
    __shared__ float2 bufA[16 * LDF], bufB[16 * LDF];
    __shared__ float2 tw[64];
    init_tw(tw);
    int tid = threadIdx.x;
    int blk = blockIdx.x;
    int bo = blk >> 2;
    int h0 = (blk & 3) << 5;              // 32 rows = 16 pairs
    int o  = bo & 63;
    const __half2* Yrow = g_Ych + (size_t)bo * NN * NHP;
    for (int i = tid; i < 16 * NN; i += 256) {
        int p = i >> 7, w = i & 127;
        int wp = (w <= 64) ? w : (NN - w);
        float2 A0 = __half22float2(Yrow[(size_t)(h0 + 2 * p)     * NHP + wp]);
        float2 A1 = __half22float2(Yrow[(size_t)(h0 + 2 * p + 1) * NHP + wp]);
        if (w > 64) { A0.y = -A0.y; A1.y = -A1.y; }
        bufA[p * LDF + w] = make_float2(A0.x - A1.y, A0.y + A1.x);
    }
    __syncthreads();
    fft128_block16<1>(bufA, bufB, tw);
    float bv = bias[o];
    const float scale = 1.0f / 16384.0f;
    float* op = out + (size_t)bo * NN * NN;
    for (int i = tid; i < 16 * NN; i += 256) {
        int p = i >> 7, w = i & 127;
        float2 v = bufB[p * LDF + w];
        float v0 = v.x * scale + bv;
        float v1 = v.y * scale + bv;
        op[(size_t)(h0 + 2 * p)     * NN + w] = fmaxf(v0, 0.f);
        op[(size_t)(h0 + 2 * p + 1) * NN + w] = fmaxf(v1, 0.f);
    }
}

// ---------------- launch ----------------
extern "C" void kernel_launch(void* const* d_in, const int* in_sizes, int n_in,
                              void* d_out, int out_size) {
    const float* x    = (const float*)d_in[0];
    const float* wr   = (const float*)d_in[1];
    const float* wi   = (const float*)d_in[2];
    const float* bias = (const float*)d_in[3];
    float* out = (float*)d_out;

    k1_rowfft <<<NBC * 4, 256>>>(x);             // 8192 blocks
    kw_weff   <<<NC * NN * 5, 256>>>(wr, wi);    // 40960 blocks
    k2_colfft <<<NB * NH * 4, 256>>>();          // 8320 blocks
    k3_contract<<<NFREQ, 128>>>();               // 8320 blocks
    k4_colifft<<<(NBO / 4) * 17, 256>>>();       // 8704 blocks
    k5_rowifft<<<NBO * 4, 256>>>(bias, out);     // 8192 blocks
}

// round 14
// speedup vs baseline: 1.2391x; 1.0147x over previous
#include <cuda_runtime.h>
#include <cuda_fp16.h>

// Problem dims
#define NN    128            // H == W == kernel_size
#define NH    65             // half-spectrum width (N/2+1)
#define NHP   68             // padded row stride for Yc
#define NB    32             // batch
#define NC    64             // in channels
#define NO    64             // out channels
#define NBC   (NB*NC)        // 2048
#define NBO   (NB*NO)        // 2048
#define NFREQ (NH*NN)        // 8320, f = wp*128 + h
#define LDF   129            // smem FFT row stride

// ---------------- scratch (device globals; allocation-free rule) ----------------
__device__ __half2 g_X1h[(size_t)NBC * NH * NN];    // [b*c][wp][h]   fp16 (r,i)
__device__ __half2 g_Xfh[(size_t)NFREQ * NB * NC];  // [f][b][c]      fp16 (r,i)
__device__ __half2 g_Wf[(size_t)NFREQ * NC * NO];   // [f][c][o]      fp16 (r,i)
__device__ __half2 g_Yfh[(size_t)NFREQ * NB * NO];  // [f][b][o]      fp16 (r,i)
__device__ __half2 g_Ych[(size_t)NBO * NN * NHP];   // [bo][h][wp]    fp16 (r,i)

__device__ __forceinline__ unsigned h2u(__half2 h) { return *(unsigned*)&h; }

// ---------------- FFT helpers ----------------
__device__ __forceinline__ void init_tw(float2* tw) {
    int tid = threadIdx.x;
    if (tid < 64) {
        float s, c;
        sincospif(-(float)tid * (1.0f / 64.0f), &s, &c);
        tw[tid] = make_float2(c, s);
    }
}

__device__ __forceinline__ float2 f2add(float2 a, float2 b) { return make_float2(a.x + b.x, a.y + b.y); }
__device__ __forceinline__ float2 f2sub(float2 a, float2 b) { return make_float2(a.x - b.x, a.y - b.y); }

template <int SIGN>
__device__ __forceinline__ float2 cmul_tw(float2 w, float2 z) {
    float wy = (SIGN < 0) ? w.y : -w.y;
    return make_float2(z.x * w.x - z.y * wy, z.x * wy + z.y * w.x);
}

#define SWZI(p) ((p) ^ ((((unsigned)(p)) >> 4) & 7))

// Fused 3x radix-2 (= radix-8) Stockham group. 16 threads per FFT.
template <int SIGN, int S, bool SWZ_ST, bool SWZ_LD>
__device__ __forceinline__ void radix8_group(const float2* src, float2* dst, const float2* tw) {
    int tid = threadIdx.x;
    int fi = tid >> 4;
    int i  = tid & 15;
    const int tk = i & ~(S - 1);
    const float2* Sr = src + fi * LDF;
    float2* Dr = dst + fi * LDF;

    float2 a[8];
#pragma unroll
    for (int k = 0; k < 8; k++) {
        int p = i + 16 * k;
        if (SWZ_LD) p = SWZI(p);
        a[k] = Sr[p];
    }
    float2 v[4], u[4];
#pragma unroll
    for (int k = 0; k < 4; k++) {
        v[k] = f2add(a[k], a[k + 4]);
        u[k] = cmul_tw<SIGN>(tw[tk + 16 * k], f2sub(a[k], a[k + 4]));
    }
    float2 w0 = tw[2 * tk], w1 = tw[2 * tk + 32];
    float2 g[4], h[4];
    g[0] = f2add(v[0], v[2]);  g[2] = cmul_tw<SIGN>(w0, f2sub(v[0], v[2]));
    g[1] = f2add(u[0], u[2]);  g[3] = cmul_tw<SIGN>(w0, f2sub(u[0], u[2]));
    h[0] = f2add(v[1], v[3]);  h[2] = cmul_tw<SIGN>(w1, f2sub(v[1], v[3]));
    h[1] = f2add(u[1], u[3]);  h[3] = cmul_tw<SIGN>(w1, f2sub(u[1], u[3]));
    float2 w2 = tw[4 * tk];
    float2 e[8];
#pragma unroll
    for (int k = 0; k < 4; k++) {
        e[k]     = f2add(g[k], h[k]);
        e[k + 4] = cmul_tw<SIGN>(w2, f2sub(g[k], h[k]));
    }
    const int Q = i + 7 * tk;
#pragma unroll
    for (int k = 0; k < 8; k++) {
        int p = Q + k * S;
        if (SWZ_ST) p = SWZI(p);
        Dr[p] = e[k];
    }
}

// 16 FFTs of length 128 per 256-thread block. Input bufA, result bufB.
template <int SIGN>
__device__ __forceinline__ void fft128_block16(float2* bufA, float2* bufB, const float2* tw) {
    radix8_group<SIGN, 1, true,  false>(bufA, bufB, tw);
    __syncthreads();
    radix8_group<SIGN, 8, false, true >(bufB, bufA, tw);
    __syncthreads();
    int tid = threadIdx.x;
#pragma unroll
    for (int itb = 0; itb < 4; itb++) {
        int it  = tid + itb * 256;
        int f2  = it >> 6;
        int idx = it & 63;
        float2 x = bufA[f2 * LDF + idx];
        float2 y = bufA[f2 * LDF + idx + 64];
        bufB[f2 * LDF + idx]      = f2add(x, y);
        bufB[f2 * LDF + idx + 64] = f2sub(x, y);
    }
    __syncthreads();
}

// ---------------- K1: forward row FFT with real-pair packing, fp16 output.
__global__ void __launch_bounds__(256) k1_rowfft(const float* __restrict__ x) {
    __shared__ float2 bufA[16 * LDF], bufB[16 * LDF];
    __shared__ float2 tw[64];
    init_tw(tw);
    int tid = threadIdx.x;
    int blk = blockIdx.x;
    int bc = blk >> 2;
    int h0 = (blk & 3) << 5;              // 32 rows
    const float* xp = x + (size_t)bc * NN * NN + (size_t)h0 * NN;
    for (int i = tid; i < 16 * NN; i += 256) {
        int p = i >> 7, w = i & 127;
        bufA[p * LDF + w] = make_float2(xp[(2 * p) * NN + w], xp[(2 * p + 1) * NN + w]);
    }
    __syncthreads();
    fft128_block16<-1>(bufA, bufB, tw);
    __half2* out = g_X1h + (size_t)bc * NH * NN;
    for (int i = tid; i < NH * 16; i += 256) {
        int p = i & 15, wp = i >> 4;
        float2 A = bufB[p * LDF + wp];
        float2 B = bufB[p * LDF + ((NN - wp) & 127)];
        __half2 X0 = __floats2half2_rn(0.5f * (A.x + B.x), 0.5f * (A.y - B.y));
        __half2 X1 = __floats2half2_rn(0.5f * (A.y + B.y), 0.5f * (B.x - A.x));
        *(uint2*)&out[(size_t)wp * NN + h0 + 2 * p] = make_uint2(h2u(X0), h2u(X1));
    }
}

// ---------------- K2: forward column FFT, scatter to freq-major [f][b][c], fp16 out
__global__ void __launch_bounds__(256) k2_colfft() {
    __shared__ float2 bufA[16 * LDF], bufB[16 * LDF];
    __shared__ float2 tw[64];
    init_tw(tw);
    int tid = threadIdx.x;
    int blk = blockIdx.x;
    int b   = blk / (NH * 4);
    int rem = blk % (NH * 4);
    int wp  = rem >> 2;
    int c0  = (rem & 3) << 4;
    for (int i = tid; i < 16 * NN; i += 256) {
        int h = i & 127, cl = i >> 7;
        bufA[cl * LDF + h] = __half22float2(
            g_X1h[((size_t)(b * NC + c0 + cl) * NH + wp) * NN + h]);
    }
    __syncthreads();
    fft128_block16<-1>(bufA, bufB, tw);
    for (int i = tid; i < 16 * NN; i += 256) {
        int cl = i & 15, h = i >> 4;
        float2 v = bufB[cl * LDF + h];
        g_Xfh[((size_t)(wp * NN + h)) * NBC + b * NC + c0 + cl] =
            __floats2half2_rn(v.x, v.y);
    }
}

// ---------------- KW: full-row mirror pairing. Block = (c, hp), hp in [0,64].
// Reads ENTIRE rows h=hp and h2=128-hp of wr/wi (512B contiguous per
// (o,row,array); every element read exactly once) and produces BOTH output
// rows: Weff(wp,h) = 0.5*(wr_h[wp]+wr_h2[w2], wi_h[wp]-wi_h2[w2]), w2=(128-wp)&127.
// Stages 4 o's at a time in smem. Row stride 132: 16B-aligned rows (fixes the
// misaligned float4 store of the 129-stride version) AND conflict-free compute
// reads (bank = oc*8 + ro*4 + wp mod 32, all distinct per warp).
#define KWO 4
#define LDW 132
__global__ void __launch_bounds__(256) kw_weff(const float* __restrict__ wr,
                                               const float* __restrict__ wi) {
    __shared__ __align__(16) float Sr[KWO][2][LDW];   // [oc][row: 0=h,1=h2][w]
    __shared__ __align__(16) float Si[KWO][2][LDW];
    int tid = threadIdx.x;
    int blk = blockIdx.x;                 // c*65 + hp
    int c   = blk / NH;
    int hp  = blk % NH;
    int h   = hp;
    int h2  = (NN - h) & 127;
    bool self = (h2 == h);                // h = 0 or 64

    for (int o0 = 0; o0 < NO; o0 += KWO) {
        // load: 2 arrays x KWO o's x 2 rows x 32 float4 = 512 float4
        for (int i = tid; i < 512; i += 256) {
            int q   = i & 31;
            int r   = (i >> 5) & 1;
            int oc  = (i >> 6) & 3;
            int arr = i >> 8;
            const float* src = (arr ? wi : wr) +
                (size_t)((o0 + oc) * NC + c) * (NN * NN) + (size_t)(r ? h2 : h) * NN;
            float4 v = *(const float4*)&src[q * 4];
            float* dst = (arr ? &Si[oc][r][0] : &Sr[oc][r][0]);
            *(float4*)&dst[q * 4] = v;
        }
        __syncthreads();
        // compute + store: oc fastest for 16B-coalesced stores
        for (int i = tid; i < KWO * 2 * NH; i += 256) {
            int oc   = i & 3;
            int orow = (i >> 2) & 1;
            int wp   = i >> 3;
            if (orow & (int)self) continue;   // self-paired row: emit once
            int w2 = (NN - wp) & 127;
            int ro = orow, rm = orow ^ 1;
            float a = 0.5f * (Sr[oc][ro][wp] + Sr[oc][rm][w2]);
            float b = 0.5f * (Si[oc][ro][wp] - Si[oc][rm][w2]);
            int row_h = orow ? h2 : h;
            g_Wf[((size_t)(wp * NN + row_h)) * (NC * NO) + c * NO + o0 + oc] =
                __floats2half2_rn(a, b);
        }
        __syncthreads();
    }
}

// ---------------- K3: per-frequency complex GEMM via tensor cores, plane form.
// Y[b][o] = sum_c X[b][c]*W[c][o] (complex) as 4 real GEMM chains on
// deinterleaved fp16 planes: Yr = (Xr@Wr) - (Xi@Wi), Yi = (Xr@Wi) + (Xi@Wr).
// Separate accumulators avoid any negated plane; products exact, fp32 accum.
// 256 threads = 8 warps; warp w owns o-range [8w, 8w+8); K=64 in 4 k-steps.
#define LDP 72   // plane row stride (halves): 144B rows (16B-aligned)
__global__ void __launch_bounds__(256) k3_contract() {
    __shared__ __align__(16) __half Xr_s[NB][LDP], Xi_s[NB][LDP];   // 9.2 KB
    __shared__ __align__(16) __half Wr_s[NC][LDP], Wi_s[NC][LDP];   // 18.4 KB
    int tid = threadIdx.x;
    int lane = tid & 31, warp = tid >> 5;
    int f = blockIdx.x;

    // A fill: deinterleave g_Xfh row (uint4 = 4 half2 = 4 c's of one b)
    const uint4* __restrict__ Xg4 = (const uint4*)(g_Xfh + (size_t)f * NBC);
    for (int i = tid; i < 512; i += 256) {
        uint4 v = Xg4[i];
        int b = i >> 4, c0 = (i & 15) << 2;
        __half2* hv = (__half2*)&v;
        *(uint2*)&Xr_s[b][c0] = make_uint2(h2u(__lows2half2(hv[0], hv[1])),
                                           h2u(__lows2half2(hv[2], hv[3])));
        *(uint2*)&Xi_s[b][c0] = make_uint2(h2u(__highs2half2(hv[0], hv[1])),
                                           h2u(__highs2half2(hv[2], hv[3])));
    }
    // B fill: deinterleave g_Wf row
    const uint4* __restrict__ Wg4 = (const uint4*)(g_Wf + (size_t)f * (NC * NO));
    for (int i = tid; i < 1024; i += 256) {
        uint4 v = Wg4[i];
        int c = i >> 4, o0 = (i & 15) << 2;
        __half2* hv = (__half2*)&v;
        *(uint2*)&Wr_s[c][o0] = make_uint2(h2u(__lows2half2(hv[0], hv[1])),
                                           h2u(__lows2half2(hv[2], hv[3])));
        *(uint2*)&Wi_s[c][o0] = make_uint2(h2u(__highs2half2(hv[0], hv[1])),
                                           h2u(__highs2half2(hv[2], hv[3])));
    }
    __syncthreads();

    int ob = warp << 3;                   // 8 o's per warp
    float r1[2][4], r2[2][4], yi[2][4];
#pragma unroll
    for (int mt = 0; mt < 2; mt++)
#pragma unroll
        for (int r = 0; r < 4; r++) { r1[mt][r] = 0.f; r2[mt][r] = 0.f; yi[mt][r] = 0.f; }

#pragma unroll
    for (int k = 0; k < 4; k++) {
        unsigned axr[2][4], axi[2][4], bwr[2], bwi[2];
#pragma unroll
        for (int mt = 0; mt < 2; mt++) {
            unsigned addr = (unsigned)__cvta_generic_to_shared(
                &Xr_s[mt * 16 + (lane & 15)][k * 16 + 8 * (lane >> 4)]);
            asm volatile("ldmatrix.sync.aligned.m8n8.x4.shared.b16 {%0,%1,%2,%3}, [%4];"
                : "=r"(axr[mt][0]), "=r"(axr[mt][1]), "=r"(axr[mt][2]), "=r"(axr[mt][3])
                : "r"(addr));
            addr = (unsigned)__cvta_generic_to_shared(
                &Xi_s[mt * 16 + (lane & 15)][k * 16 + 8 * (lane >> 4)]);
            asm volatile("ldmatrix.sync.aligned.m8n8.x4.shared.b16 {%0,%1,%2,%3}, [%4];"
                : "=r"(axi[mt][0]), "=r"(axi[mt][1]), "=r"(axi[mt][2]), "=r"(axi[mt][3])
                : "r"(addr));
        }
        {
            unsigned addr = (unsigned)__cvta_generic_to_shared(
                &Wr_s[k * 16 + (lane & 15)][ob]);
            asm volatile("ldmatrix.sync.aligned.m8n8.x2.trans.shared.b16 {%0,%1}, [%2];"
                : "=r"(bwr[0]), "=r"(bwr[1]) : "r"(addr));
            addr = (unsigned)__cvta_generic_to_shared(
                &Wi_s[k * 16 + (lane & 15)][ob]);
            asm volatile("ldmatrix.sync.aligned.m8n8.x2.trans.shared.b16 {%0,%1}, [%2];"
                : "=r"(bwi[0]), "=r"(bwi[1]) : "r"(addr));
        }
#pragma unroll
        for (int mt = 0; mt < 2; mt++) {
            asm volatile("mma.sync.aligned.m16n8k16.row.col.f32.f16.f16.f32 "
                "{%0,%1,%2,%3}, {%4,%5,%6,%7}, {%8,%9}, {%0,%1,%2,%3};"
                : "+f"(r1[mt][0]), "+f"(r1[mt][1]), "+f"(r1[mt][2]), "+f"(r1[mt][3])
                : "r"(axr[mt][0]), "r"(axr[mt][1]), "r"(axr[mt][2]), "r"(axr[mt][3]),
                  "r"(bwr[0]), "r"(bwr[1]));
            asm volatile("mma.sync.aligned.m16n8k16.row.col.f32.f16.f16.f32 "
                "{%0,%1,%2,%3}, {%4,%5,%6,%7}, {%8,%9}, {%0,%1,%2,%3};"
                : "+f"(r2[mt][0]), "+f"(r2[mt][1]), "+f"(r2[mt][2]), "+f"(r2[mt][3])
                : "r"(axi[mt][0]), "r"(axi[mt][1]), "r"(axi[mt][2]), "r"(axi[mt][3]),
                  "r"(bwi[0]), "r"(bwi[1]));
            asm volatile("mma.sync.aligned.m16n8k16.row.col.f32.f16.f16.f32 "
                "{%0,%1,%2,%3}, {%4,%5,%6,%7}, {%8,%9}, {%0,%1,%2,%3};"
                : "+f"(yi[mt][0]), "+f"(yi[mt][1]), "+f"(yi[mt][2]), "+f"(yi[mt][3])
                : "r"(axr[mt][0]), "r"(axr[mt][1]), "r"(axr[mt][2]), "r"(axr[mt][3]),
                  "r"(bwi[0]), "r"(bwi[1]));
            asm volatile("mma.sync.aligned.m16n8k16.row.col.f32.f16.f16.f32 "
                "{%0,%1,%2,%3}, {%4,%5,%6,%7}, {%8,%9}, {%0,%1,%2,%3};"
                : "+f"(yi[mt][0]), "+f"(yi[mt][1]), "+f"(yi[mt][2]), "+f"(yi[mt][3])
                : "r"(axi[mt][0]), "r"(axi[mt][1]), "r"(axi[mt][2]), "r"(axi[mt][3]),
                  "r"(bwr[0]), "r"(bwr[1]));
        }
    }

    // Epilogue: c0,c1 = (row g, o = ob+2*tig, +1); c2,c3 = row g+8.
    __half2* __restrict__ Ygh = g_Yfh + (size_t)f * (NB * NO);
    int g = lane >> 2, tig = lane & 3;
    int o0 = ob + (tig << 1);
#pragma unroll
    for (int mt = 0; mt < 2; mt++) {
        int br = mt * 16 + g;
        __half2 e0 = __floats2half2_rn(r1[mt][0] - r2[mt][0], yi[mt][0]);
        __half2 e1 = __floats2half2_rn(r1[mt][1] - r2[mt][1], yi[mt][1]);
        __half2 e2 = __floats2half2_rn(r1[mt][2] - r2[mt][2], yi[mt][2]);
        __half2 e3 = __floats2half2_rn(r1[mt][3] - r2[mt][3], yi[mt][3]);
        *(uint2*)&Ygh[br * NO + o0]       = make_uint2(h2u(e0), h2u(e1));
        *(uint2*)&Ygh[(br + 8) * NO + o0] = make_uint2(h2u(e2), h2u(e3));
    }
}

// ---------------- K4: inverse column FFT (along h), to [bo][h][wp] fp16 (padded)
__global__ void __launch_bounds__(256) k4_colifft() {
    __shared__ float2 bufA[16 * LDF], bufB[16 * LDF];
    __shared__ float2 tw[64];
    init_tw(tw);
    int tid = threadIdx.x;
    int blk = blockIdx.x;
    int bt = blk / 17;
    int wt = blk % 17;
    int bo0 = bt << 2;
    int wp0 = wt << 2;
    for (int i = tid; i < 4 * NN; i += 256) {          // 512 uint4 loads (4 bo each)
        int wl = i & 3, h = i >> 2;
        int wp = wp0 + wl;
        uint4 v = make_uint4(0u, 0u, 0u, 0u);
        if (wp < NH)
            v = *(const uint4*)&g_Yfh[((size_t)(wp * NN + h)) * NBO + bo0];
        const unsigned* vp = &v.x;
#pragma unroll
        for (int bl = 0; bl < 4; bl++) {
            __half2 hv = *(__half2*)&vp[bl];
            bufA[((wl << 2) + bl) * LDF + h] = __half22float2(hv);
        }
    }
    __syncthreads();
    fft128_block16<1>(bufA, bufB, tw);
    for (int i = tid; i < 16 * NN; i += 256) {
        int wl = i & 3, bl = (i >> 2) & 3, h = i >> 4;
        int wp = wp0 + wl;
        int fi = (wl << 2) + bl;
        if (wp < NH) {
            float2 v = bufB[fi * LDF + h];
            g_Ych[((size_t)(bo0 + bl) * NN + h) * NHP + wp] = __floats2half2_rn(v.x, v.y);
        }
    }
}

// ---------------- K5: inverse row FFT with real-pair packing + bias + relu
__global__ void __launch_bounds__(256) k5_rowifft(const float* __restrict__ bias,
                                                  float* __restrict__ out) {
    __shared__ float2 bufA[16 * LDF], bufB[16 * LDF];
    __shared__ float2 tw[64];
    init_tw(tw);
    int tid = threadIdx.x;
    int blk = blockIdx.x;
    int bo = blk >> 2;
    int h0 = (blk & 3) << 5;              // 32 rows = 16 pairs
    int o  = bo & 63;
    const __half2* Yrow = g_Ych + (size_t)bo * NN * NHP;
    for (int i = tid; i < 16 * NN; i += 256) {
        int p = i >> 7, w = i & 127;
        int wp = (w <= 64) ? w : (NN - w);
        float2 A0 = __half22float2(Yrow[(size_t)(h0 + 2 * p)     * NHP + wp]);
        float2 A1 = __half22float2(Yrow[(size_t)(h0 + 2 * p + 1) * NHP + wp]);
        if (w > 64) { A0.y = -A0.y; A1.y = -A1.y; }
        bufA[p * LDF + w] = make_float2(A0.x - A1.y, A0.y + A1.x);
    }
    __syncthreads();
    fft128_block16<1>(bufA, bufB, tw);
    float bv = bias[o];
    const float scale = 1.0f / 16384.0f;
    float* op = out + (size_t)bo * NN * NN;
    for (int i = tid; i < 16 * NN; i += 256) {
        int p = i >> 7, w = i & 127;
        float2 v = bufB[p * LDF + w];
        float v0 = v.x * scale + bv;
        float v1 = v.y * scale + bv;
        op[(size_t)(h0 + 2 * p)     * NN + w] = fmaxf(v0, 0.f);
        op[(size_t)(h0 + 2 * p + 1) * NN + w] = fmaxf(v1, 0.f);
    }
}

// ---------------- launch ----------------
extern "C" void kernel_launch(void* const* d_in, const int* in_sizes, int n_in,
                              void* d_out, int out_size) {
    const float* x    = (const float*)d_in[0];
    const float* wr   = (const float*)d_in[1];
    const float* wi   = (const float*)d_in[2];
    const float* bias = (const float*)d_in[3];
    float* out = (float*)d_out;

    k1_rowfft <<<NBC * 4, 256>>>(x);             // 8192 blocks
    kw_weff   <<<NC * NH, 256>>>(wr, wi);        // 4160 blocks
    k2_colfft <<<NB * NH * 4, 256>>>();          // 8320 blocks
    k3_contract<<<NFREQ, 256>>>();               // 8320 blocks
    k4_colifft<<<(NBO / 4) * 17, 256>>>();       // 8704 blocks
    k5_rowifft<<<NBO * 4, 256>>>(bias, out);     // 8192 blocks
}

// round 16
// speedup vs baseline: 1.3252x; 1.0695x over previous
#include <cuda_runtime.h>
#include <cuda_fp16.h>

// Problem dims
#define NN    128            // H == W == kernel_size
#define NH    65             // half-spectrum width (N/2+1)
#define NHP   68             // padded row stride for Yc
#define NB    32             // batch
#define NC    64             // in channels
#define NO    64             // out channels
#define NBC   (NB*NC)        // 2048
#define NBO   (NB*NO)        // 2048
#define NFREQ (NH*NN)        // 8320, f = wp*128 + h
#define LDF   129            // smem FFT row stride

// ---------------- scratch (device globals; allocation-free rule) ----------------
__device__ __half2 g_X1h[(size_t)NBC * NH * NN];    // [b*c][wp][h]   fp16 (r,i)
__device__ __half2 g_Xfh[(size_t)NFREQ * NB * NC];  // [f][b][c]      fp16 (r,i)
__device__ __half2 g_Wf[(size_t)NFREQ * NC * NO];   // [f][c][o]      fp16 (r,i)
__device__ __half2 g_Yfh[(size_t)NFREQ * NB * NO];  // [f][b][o]      fp16 (r,i)
__device__ __half2 g_Ych[(size_t)NBO * NN * NHP];   // [bo][h][wp]    fp16 (r,i)

__device__ __forceinline__ unsigned h2u(__half2 h) { return *(unsigned*)&h; }

// ---------------- FFT helpers ----------------
__device__ __forceinline__ void init_tw(float2* tw) {
    int tid = threadIdx.x;
    if (tid < 64) {
        float s, c;
        sincospif(-(float)tid * (1.0f / 64.0f), &s, &c);
        tw[tid] = make_float2(c, s);
    }
}

__device__ __forceinline__ float2 f2add(float2 a, float2 b) { return make_float2(a.x + b.x, a.y + b.y); }
__device__ __forceinline__ float2 f2sub(float2 a, float2 b) { return make_float2(a.x - b.x, a.y - b.y); }

template <int SIGN>
__device__ __forceinline__ float2 cmul_tw(float2 w, float2 z) {
    float wy = (SIGN < 0) ? w.y : -w.y;
    return make_float2(z.x * w.x - z.y * wy, z.x * wy + z.y * w.x);
}

#define SWZI(p) ((p) ^ ((((unsigned)(p)) >> 4) & 7))

// Fused 3x radix-2 (= radix-8) Stockham group. 16 threads per FFT.
template <int SIGN, int S, bool SWZ_ST, bool SWZ_LD>
__device__ __forceinline__ void radix8_group(const float2* src, float2* dst, const float2* tw) {
    int tid = threadIdx.x;
    int fi = tid >> 4;
    int i  = tid & 15;
    const int tk = i & ~(S - 1);
    const float2* Sr = src + fi * LDF;
    float2* Dr = dst + fi * LDF;

    float2 a[8];
#pragma unroll
    for (int k = 0; k < 8; k++) {
        int p = i + 16 * k;
        if (SWZ_LD) p = SWZI(p);
        a[k] = Sr[p];
    }
    float2 v[4], u[4];
#pragma unroll
    for (int k = 0; k < 4; k++) {
        v[k] = f2add(a[k], a[k + 4]);
        u[k] = cmul_tw<SIGN>(tw[tk + 16 * k], f2sub(a[k], a[k + 4]));
    }
    float2 w0 = tw[2 * tk], w1 = tw[2 * tk + 32];
    float2 g[4], h[4];
    g[0] = f2add(v[0], v[2]);  g[2] = cmul_tw<SIGN>(w0, f2sub(v[0], v[2]));
    g[1] = f2add(u[0], u[2]);  g[3] = cmul_tw<SIGN>(w0, f2sub(u[0], u[2]));
    h[0] = f2add(v[1], v[3]);  h[2] = cmul_tw<SIGN>(w1, f2sub(v[1], v[3]));
    h[1] = f2add(u[1], u[3]);  h[3] = cmul_tw<SIGN>(w1, f2sub(u[1], u[3]));
    float2 w2 = tw[4 * tk];
    float2 e[8];
#pragma unroll
    for (int k = 0; k < 4; k++) {
        e[k]     = f2add(g[k], h[k]);
        e[k + 4] = cmul_tw<SIGN>(w2, f2sub(g[k], h[k]));
    }
    const int Q = i + 7 * tk;
#pragma unroll
    for (int k = 0; k < 8; k++) {
        int p = Q + k * S;
        if (SWZ_ST) p = SWZI(p);
        Dr[p] = e[k];
    }
}

// 16 FFTs of length 128 per 256-thread block. Input bufA, result bufB.
template <int SIGN>
__device__ __forceinline__ void fft128_block16(float2* bufA, float2* bufB, const float2* tw) {
    radix8_group<SIGN, 1, true,  false>(bufA, bufB, tw);
    __syncthreads();
    radix8_group<SIGN, 8, false, true >(bufB, bufA, tw);
    __syncthreads();
    int tid = threadIdx.x;
#pragma unroll
    for (int itb = 0; itb < 4; itb++) {
        int it  = tid + itb * 256;
        int f2  = it >> 6;
        int idx = it & 63;
        float2 x = bufA[f2 * LDF + idx];
        float2 y = bufA[f2 * LDF + idx + 64];
        bufB[f2 * LDF + idx]      = f2add(x, y);
        bufB[f2 * LDF + idx + 64] = f2sub(x, y);
    }
    __syncthreads();
}

// ---------------- K1: forward row FFT with real-pair packing, fp16 output.
__global__ void __launch_bounds__(256) k1_rowfft(const float* __restrict__ x) {
    __shared__ float2 bufA[16 * LDF], bufB[16 * LDF];
    __shared__ float2 tw[64];
    init_tw(tw);
    int tid = threadIdx.x;
    int blk = blockIdx.x;
    int bc = blk >> 2;
    int h0 = (blk & 3) << 5;              // 32 rows
    const float* xp = x + (size_t)bc * NN * NN + (size_t)h0 * NN;
    for (int i = tid; i < 16 * NN; i += 256) {
        int p = i >> 7, w = i & 127;
        bufA[p * LDF + w] = make_float2(xp[(2 * p) * NN + w], xp[(2 * p + 1) * NN + w]);
    }
    __syncthreads();
    fft128_block16<-1>(bufA, bufB, tw);
    __half2* out = g_X1h + (size_t)bc * NH * NN;
    for (int i = tid; i < NH * 16; i += 256) {
        int p = i & 15, wp = i >> 4;
        float2 A = bufB[p * LDF + wp];
        float2 B = bufB[p * LDF + ((NN - wp) & 127)];
        __half2 X0 = __floats2half2_rn(0.5f * (A.x + B.x), 0.5f * (A.y - B.y));
        __half2 X1 = __floats2half2_rn(0.5f * (A.y + B.y), 0.5f * (B.x - A.x));
        *(uint2*)&out[(size_t)wp * NN + h0 + 2 * p] = make_uint2(h2u(X0), h2u(X1));
    }
}

// ---------------- K2: forward column FFT, scatter to freq-major [f][b][c], fp16 out
__global__ void __launch_bounds__(256) k2_colfft() {
    __shared__ float2 bufA[16 * LDF], bufB[16 * LDF];
    __shared__ float2 tw[64];
    init_tw(tw);
    int tid = threadIdx.x;
    int blk = blockIdx.x;
    int b   = blk / (NH * 4);
    int rem = blk % (NH * 4);
    int wp  = rem >> 2;
    int c0  = (rem & 3) << 4;
    for (int i = tid; i < 16 * NN; i += 256) {
        int h = i & 127, cl = i >> 7;
        bufA[cl * LDF + h] = __half22float2(
            g_X1h[((size_t)(b * NC + c0 + cl) * NH + wp) * NN + h]);
    }
    __syncthreads();
    fft128_block16<-1>(bufA, bufB, tw);
    for (int i = tid; i < 16 * NN; i += 256) {
        int cl = i & 15, h = i >> 4;
        float2 v = bufB[cl * LDF + h];
        g_Xfh[((size_t)(wp * NN + h)) * NBC + b * NC + c0 + cl] =
            __floats2half2_rn(v.x, v.y);
    }
}

// ---------------- KW: full-row mirror pairing + cp.async double-buffer pipeline.
// Block = (c, hp), hp in [0,64]. Reads entire rows h=hp and h2=128-hp of wr/wi
// (aligned float4s, every element exactly once) and produces both output rows.
// o-chunks of KWO=4 are pipelined 2 deep with cp.async so chunk k+2's DRAM
// latency overlaps chunk k's compute/stores.
#define KWO 4
#define LDW 132
__global__ void __launch_bounds__(256) kw_weff(const float* __restrict__ wr,
                                               const float* __restrict__ wi) {
    __shared__ __align__(16) float Sr[2][KWO][2][LDW];   // [buf][oc][row][w]
    __shared__ __align__(16) float Si[2][KWO][2][LDW];
    int tid = threadIdx.x;
    int blk = blockIdx.x;                 // c*65 + hp
    int c   = blk / NH;
    int hp  = blk % NH;
    int h   = hp;
    int h2  = (NN - h) & 127;
    int self = (h2 == h);                 // h = 0 or 64

    // issue one o-chunk's loads: 2 arrays x KWO o's x 2 rows x 32 float4 = 512
    auto issue = [&](int o0, int buf) {
#pragma unroll
        for (int ii = 0; ii < 2; ii++) {
            int i   = tid + ii * 256;
            int q   = i & 31;
            int r   = (i >> 5) & 1;
            int oc  = (i >> 6) & 3;
            int arr = i >> 8;
            const float* src = (arr ? wi : wr) +
                (size_t)((o0 + oc) * NC + c) * (NN * NN) +
                (size_t)(r ? h2 : h) * NN + q * 4;
            float* dst = arr ? &Si[buf][oc][r][q * 4] : &Sr[buf][oc][r][q * 4];
            unsigned da = (unsigned)__cvta_generic_to_shared(dst);
            asm volatile("cp.async.ca.shared.global [%0], [%1], 16;"
                         :: "r"(da), "l"(src) : "memory");
        }
        asm volatile("cp.async.commit_group;" ::: "memory");
    };

    issue(0, 0);
    issue(KWO, 1);
    for (int ph = 0; ph < 16; ph++) {
        int o0  = ph * KWO;
        int buf = ph & 1;
        if (ph == 15) asm volatile("cp.async.wait_group 0;" ::: "memory");
        else          asm volatile("cp.async.wait_group 1;" ::: "memory");
        __syncthreads();
        // compute + store (bank = 8*oc + 4*ro + wp mod 32: conflict-free)
        for (int i = tid; i < KWO * 2 * NH; i += 256) {
            int oc   = i & 3;
            int orow = (i >> 2) & 1;
            int wp   = i >> 3;
            if (orow & self) continue;    // self-paired row: emit once
            int w2 = (NN - wp) & 127;
            int ro = orow, rm = orow ^ 1;
            float a = 0.5f * (Sr[buf][oc][ro][wp] + Sr[buf][oc][rm][w2]);
            float b = 0.5f * (Si[buf][oc][ro][wp] - Si[buf][oc][rm][w2]);
            int row_h = orow ? h2 : h;
            g_Wf[((size_t)(wp * NN + row_h)) * (NC * NO) + c * NO + o0 + oc] =
                __floats2half2_rn(a, b);
        }
        __syncthreads();
        if (ph + 2 < 16) issue(o0 + 2 * KWO, buf);
    }
}

// ---------------- K3: per-frequency complex GEMM via tensor cores, plane form.
// Yr = (Xr@Wr) - (Xi@Wi), Yi = (Xr@Wi) + (Xi@Wr); products exact, fp32 accum.
// 256 threads = 8 warps; warp w owns o-range [8w, 8w+8); K=64 in 4 k-steps.
#define LDP 72   // plane row stride (halves): 144B rows (16B-aligned)
__global__ void __launch_bounds__(256) k3_contract() {
    __shared__ __align__(16) __half Xr_s[NB][LDP], Xi_s[NB][LDP];   // 9.2 KB
    __shared__ __align__(16) __half Wr_s[NC][LDP], Wi_s[NC][LDP];   // 18.4 KB
    int tid = threadIdx.x;
    int lane = tid & 31, warp = tid >> 5;
    int f = blockIdx.x;

    // A fill: deinterleave g_Xfh row (uint4 = 4 half2 = 4 c's of one b)
    const uint4* __restrict__ Xg4 = (const uint4*)(g_Xfh + (size_t)f * NBC);
    for (int i = tid; i < 512; i += 256) {
        uint4 v = Xg4[i];
        int b = i >> 4, c0 = (i & 15) << 2;
        __half2* hv = (__half2*)&v;
        *(uint2*)&Xr_s[b][c0] = make_uint2(h2u(__lows2half2(hv[0], hv[1])),
                                           h2u(__lows2half2(hv[2], hv[3])));
        *(uint2*)&Xi_s[b][c0] = make_uint2(h2u(__highs2half2(hv[0], hv[1])),
                                           h2u(__highs2half2(hv[2], hv[3])));
    }
    // B fill: deinterleave g_Wf row
    const uint4* __restrict__ Wg4 = (const uint4*)(g_Wf + (size_t)f * (NC * NO));
    for (int i = tid; i < 1024; i += 256) {
        uint4 v = Wg4[i];
        int c = i >> 4, o0 = (i & 15) << 2;
        __half2* hv = (__half2*)&v;
        *(uint2*)&Wr_s[c][o0] = make_uint2(h2u(__lows2half2(hv[0], hv[1])),
                                           h2u(__lows2half2(hv[2], hv[3])));
        *(uint2*)&Wi_s[c][o0] = make_uint2(h2u(__highs2half2(hv[0], hv[1])),
                                           h2u(__highs2half2(hv[2], hv[3])));
    }
    __syncthreads();

    int ob = warp << 3;                   // 8 o's per warp
    float r1[2][4], r2[2][4], yi[2][4];
#pragma unroll
    for (int mt = 0; mt < 2; mt++)
#pragma unroll
        for (int r = 0; r < 4; r++) { r1[mt][r] = 0.f; r2[mt][r] = 0.f; yi[mt][r] = 0.f; }

#pragma unroll
    for (int k = 0; k < 4; k++) {
        unsigned axr[2][4], axi[2][4], bwr[2], bwi[2];
#pragma unroll
        for (int mt = 0; mt < 2; mt++) {
            unsigned addr = (unsigned)__cvta_generic_to_shared(
                &Xr_s[mt * 16 + (lane & 15)][k * 16 + 8 * (lane >> 4)]);
            asm volatile("ldmatrix.sync.aligned.m8n8.x4.shared.b16 {%0,%1,%2,%3}, [%4];"
                : "=r"(axr[mt][0]), "=r"(axr[mt][1]), "=r"(axr[mt][2]), "=r"(axr[mt][3])
                : "r"(addr));
            addr = (unsigned)__cvta_generic_to_shared(
                &Xi_s[mt * 16 + (lane & 15)][k * 16 + 8 * (lane >> 4)]);
            asm volatile("ldmatrix.sync.aligned.m8n8.x4.shared.b16 {%0,%1,%2,%3}, [%4];"
                : "=r"(axi[mt][0]), "=r"(axi[mt][1]), "=r"(axi[mt][2]), "=r"(axi[mt][3])
                : "r"(addr));
        }
        {
            unsigned addr = (unsigned)__cvta_generic_to_shared(
                &Wr_s[k * 16 + (lane & 15)][ob]);
            asm volatile("ldmatrix.sync.aligned.m8n8.x2.trans.shared.b16 {%0,%1}, [%2];"
                : "=r"(bwr[0]), "=r"(bwr[1]) : "r"(addr));
            addr = (unsigned)__cvta_generic_to_shared(
                &Wi_s[k * 16 + (lane & 15)][ob]);
            asm volatile("ldmatrix.sync.aligned.m8n8.x2.trans.shared.b16 {%0,%1}, [%2];"
                : "=r"(bwi[0]), "=r"(bwi[1]) : "r"(addr));
        }
#pragma unroll
        for (int mt = 0; mt < 2; mt++) {
            asm volatile("mma.sync.aligned.m16n8k16.row.col.f32.f16.f16.f32 "
                "{%0,%1,%2,%3}, {%4,%5,%6,%7}, {%8,%9}, {%0,%1,%2,%3};"
                : "+f"(r1[mt][0]), "+f"(r1[mt][1]), "+f"(r1[mt][2]), "+f"(r1[mt][3])
                : "r"(axr[mt][0]), "r"(axr[mt][1]), "r"(axr[mt][2]), "r"(axr[mt][3]),
                  "r"(bwr[0]), "r"(bwr[1]));
            asm volatile("mma.sync.aligned.m16n8k16.row.col.f32.f16.f16.f32 "
                "{%0,%1,%2,%3}, {%4,%5,%6,%7}, {%8,%9}, {%0,%1,%2,%3};"
                : "+f"(r2[mt][0]), "+f"(r2[mt][1]), "+f"(r2[mt][2]), "+f"(r2[mt][3])
                : "r"(axi[mt][0]), "r"(axi[mt][1]), "r"(axi[mt][2]), "r"(axi[mt][3]),
                  "r"(bwi[0]), "r"(bwi[1]));
            asm volatile("mma.sync.aligned.m16n8k16.row.col.f32.f16.f16.f32 "
                "{%0,%1,%2,%3}, {%4,%5,%6,%7}, {%8,%9}, {%0,%1,%2,%3};"
                : "+f"(yi[mt][0]), "+f"(yi[mt][1]), "+f"(yi[mt][2]), "+f"(yi[mt][3])
                : "r"(axr[mt][0]), "r"(axr[mt][1]), "r"(axr[mt][2]), "r"(axr[mt][3]),
                  "r"(bwi[0]), "r"(bwi[1]));
            asm volatile("mma.sync.aligned.m16n8k16.row.col.f32.f16.f16.f32 "
                "{%0,%1,%2,%3}, {%4,%5,%6,%7}, {%8,%9}, {%0,%1,%2,%3};"
                : "+f"(yi[mt][0]), "+f"(yi[mt][1]), "+f"(yi[mt][2]), "+f"(yi[mt][3])
                : "r"(axi[mt][0]), "r"(axi[mt][1]), "r"(axi[mt][2]), "r"(axi[mt][3]),
                  "r"(bwr[0]), "r"(bwr[1]));
        }
    }

    // Epilogue: c0,c1 = (row g, o = ob+2*tig, +1); c2,c3 = row g+8.
    __half2* __restrict__ Ygh = g_Yfh + (size_t)f * (NB * NO);
    int g = lane >> 2, tig = lane & 3;
    int o0 = ob + (tig << 1);
#pragma unroll
    for (int mt = 0; mt < 2; mt++) {
        int br = mt * 16 + g;
        __half2 e0 = __floats2half2_rn(r1[mt][0] - r2[mt][0], yi[mt][0]);
        __half2 e1 = __floats2half2_rn(r1[mt][1] - r2[mt][1], yi[mt][1]);
        __half2 e2 = __floats2half2_rn(r1[mt][2] - r2[mt][2], yi[mt][2]);
        __half2 e3 = __floats2half2_rn(r1[mt][3] - r2[mt][3], yi[mt][3]);
        *(uint2*)&Ygh[br * NO + o0]       = make_uint2(h2u(e0), h2u(e1));
        *(uint2*)&Ygh[(br + 8) * NO + o0] = make_uint2(h2u(e2), h2u(e3));
    }
}

// ---------------- K4: inverse column FFT (along h), to [bo][h][wp] fp16 (padded)
__global__ void __launch_bounds__(256) k4_colifft() {
    __shared__ float2 bufA[16 * LDF], bufB[16 * LDF];
    __shared__ float2 tw[64];
    init_tw(tw);
    int tid = threadIdx.x;
    int blk = blockIdx.x;
    int bt = blk / 17;
    int wt = blk % 17;
    int bo0 = bt << 2;
    int wp0 = wt << 2;
    for (int i = tid; i < 4 * NN; i += 256) {          // 512 uint4 loads (4 bo each)
        int wl = i & 3, h = i >> 2;
        int wp = wp0 + wl;
        uint4 v = make_uint4(0u, 0u, 0u, 0u);
        if (wp < NH)
            v = *(const uint4*)&g_Yfh[((size_t)(wp * NN + h)) * NBO + bo0];
        const unsigned* vp = &v.x;
#pragma unroll
        for (int bl = 0; bl < 4; bl++) {
            __half2 hv = *(__half2*)&vp[bl];
            bufA[((wl << 2) + bl) * LDF + h] = __half22float2(hv);
        }
    }
    __syncthreads();
    fft128_block16<1>(bufA, bufB, tw);
    for (int i = tid; i < 16 * NN; i += 256) {
        int wl = i & 3, bl = (i >> 2) & 3, h = i >> 4;
        int wp = wp0 + wl;
        int fi = (wl << 2) + bl;
        if (wp < NH) {
            float2 v = bufB[fi * LDF + h];
            g_Ych[((size_t)(bo0 + bl) * NN + h) * NHP + wp] = __floats2half2_rn(v.x, v.y);
        }
    }
}

// ---------------- K5: inverse row FFT with real-pair packing + bias + relu
__global__ void __launch_bounds__(256) k5_rowifft(const float* __restrict__ bias,
                                                  float* __restrict__ out) {
    __shared__ float2 bufA[16 * LDF], bufB[16 * LDF];
    __shared__ float2 tw[64];
    init_tw(tw);
    int tid = threadIdx.x;
    int blk = blockIdx.x;
    int bo = blk >> 2;
    int h0 = (blk & 3) << 5;              // 32 rows = 16 pairs
    int o  = bo & 63;
    const __half2* Yrow = g_Ych + (size_t)bo * NN * NHP;
    for (int i = tid; i < 16 * NN; i += 256) {
        int p = i >> 7, w = i & 127;
        int wp = (w <= 64) ? w : (NN - w);
        float2 A0 = __half22float2(Yrow[(size_t)(h0 + 2 * p)     * NHP + wp]);
        float2 A1 = __half22float2(Yrow[(size_t)(h0 + 2 * p + 1) * NHP + wp]);
        if (w > 64) { A0.y = -A0.y; A1.y = -A1.y; }
        bufA[p * LDF + w] = make_float2(A0.x - A1.y, A0.y + A1.x);
    }
    __syncthreads();
    fft128_block16<1>(bufA, bufB, tw);
    float bv = bias[o];
    const float scale = 1.0f / 16384.0f;
    float* op = out + (size_t)bo * NN * NN;
    for (int i = tid; i < 16 * NN; i += 256) {
        int p = i >> 7, w = i & 127;
        float2 v = bufB[p * LDF + w];
        float v0 = v.x * scale + bv;
        float v1 = v.y * scale + bv;
        op[(size_t)(h0 + 2 * p)     * NN + w] = fmaxf(v0, 0.f);
        op[(size_t)(h0 + 2 * p + 1) * NN + w] = fmaxf(v1, 0.f);
    }
}

// ---------------- launch ----------------
extern "C" void kernel_launch(void* const* d_in, const int* in_sizes, int n_in,
                              void* d_out, int out_size) {
    const float* x    = (const float*)d_in[0];
    const float* wr   = (const float*)d_in[1];
    const float* wi   = (const float*)d_in[2];
    const float* bias = (const float*)d_in[3];
    float* out = (float*)d_out;

    k1_rowfft <<<NBC * 4, 256>>>(x);             // 8192 blocks
    kw_weff   <<<NC * NH, 256>>>(wr, wi);        // 4160 blocks
    k2_colfft <<<NB * NH * 4, 256>>>();          // 8320 blocks
    k3_contract<<<NFREQ, 256>>>();               // 8320 blocks
    k4_colifft<<<(NBO / 4) * 17, 256>>>();       // 8704 blocks
    k5_rowifft<<<NBO * 4, 256>>>(bias, out);     // 8192 blocks
}

// round 17
// speedup vs baseline: 1.3651x; 1.0302x over previous
#include <cuda_runtime.h>
#include <cuda_fp16.h>

// Problem dims
#define NN    128            // H == W == kernel_size
#define NH    65             // half-spectrum width (N/2+1)
#define NHP   68             // padded row stride for Yc
#define NB    32             // batch
#define NC    64             // in channels
#define NO    64             // out channels
#define NBC   (NB*NC)        // 2048
#define NBO   (NB*NO)        // 2048
#define NFREQ (NH*NN)        // 8320, f = wp*128 + h
#define LDF   129            // smem FFT row stride

// ---------------- scratch (device globals; allocation-free rule) ----------------
__device__ __half2 g_X1h[(size_t)NBC * NH * NN];    // [b*c][wp][h]   fp16 (r,i)
__device__ __half2 g_Xfh[(size_t)NFREQ * NB * NC];  // [f][b][c]      fp16 (r,i)
__device__ __half2 g_Wf[(size_t)NFREQ * NC * NO];   // [f][c][o]      fp16 (r,i)
__device__ __half2 g_Yfh[(size_t)NFREQ * NB * NO];  // [f][b][o]      fp16 (r,i)
__device__ __half2 g_Ych[(size_t)NBO * NN * NHP];   // [bo][h][wp]    fp16 (r,i)

__device__ __forceinline__ unsigned h2u(__half2 h) { return *(unsigned*)&h; }

// ---------------- FFT helpers ----------------
__device__ __forceinline__ void init_tw(float2* tw) {
    int tid = threadIdx.x;
    if (tid < 64) {
        float s, c;
        sincospif(-(float)tid * (1.0f / 64.0f), &s, &c);
        tw[tid] = make_float2(c, s);
    }
}

__device__ __forceinline__ float2 f2add(float2 a, float2 b) { return make_float2(a.x + b.x, a.y + b.y); }
__device__ __forceinline__ float2 f2sub(float2 a, float2 b) { return make_float2(a.x - b.x, a.y - b.y); }

template <int SIGN>
__device__ __forceinline__ float2 cmul_tw(float2 w, float2 z) {
    float wy = (SIGN < 0) ? w.y : -w.y;
    return make_float2(z.x * w.x - z.y * wy, z.x * wy + z.y * w.x);
}

#define SWZI(p) ((p) ^ ((((unsigned)(p)) >> 4) & 7))

// Shared radix-8 butterfly math (3 fused radix-2 stages); tk = i & ~(S-1).
template <int SIGN>
__device__ __forceinline__ void radix8_butterfly(const float2* a, float2* e, int tk, const float2* tw) {
    float2 v[4], u[4];
#pragma unroll
    for (int k = 0; k < 4; k++) {
        v[k] = f2add(a[k], a[k + 4]);
        u[k] = cmul_tw<SIGN>(tw[tk + 16 * k], f2sub(a[k], a[k + 4]));
    }
    float2 w0 = tw[2 * tk], w1 = tw[2 * tk + 32];
    float2 g[4], h[4];
    g[0] = f2add(v[0], v[2]);  g[2] = cmul_tw<SIGN>(w0, f2sub(v[0], v[2]));
    g[1] = f2add(u[0], u[2]);  g[3] = cmul_tw<SIGN>(w0, f2sub(u[0], u[2]));
    h[0] = f2add(v[1], v[3]);  h[2] = cmul_tw<SIGN>(w1, f2sub(v[1], v[3]));
    h[1] = f2add(u[1], u[3]);  h[3] = cmul_tw<SIGN>(w1, f2sub(u[1], u[3]));
    float2 w2 = tw[4 * tk];
#pragma unroll
    for (int k = 0; k < 4; k++) {
        e[k]     = f2add(g[k], h[k]);
        e[k + 4] = cmul_tw<SIGN>(w2, f2sub(g[k], h[k]));
    }
}

// First radix-8 group (strides 1,2,4): bufA -> bufB with XOR-swizzled store.
template <int SIGN>
__device__ __forceinline__ void radix8_group1(const float2* src, float2* dst, const float2* tw) {
    int tid = threadIdx.x;
    int fi = tid >> 4;
    int i  = tid & 15;
    const float2* Sr = src + fi * LDF;
    float2* Dr = dst + fi * LDF;
    float2 a[8], e[8];
#pragma unroll
    for (int k = 0; k < 8; k++) a[k] = Sr[i + 16 * k];
    radix8_butterfly<SIGN>(a, e, i, tw);      // S=1: tk = i
    const int Q = i + 7 * i;                  // = 8*i
#pragma unroll
    for (int k = 0; k < 8; k++) Dr[SWZI(Q + k)] = e[k];
}

// 16 FFTs of length 128 per 256-thread block. Input bufA, result lands in bufB.
// Group 2 (strides 8,16,32) is IN-PLACE on bufB with the final stride-64
// radix-2 fused via shfl.xor(8): thread i<8 holds positions p<64, thread i+8
// holds p+64 for the same k, so the last butterfly never touches smem.
template <int SIGN>
__device__ __forceinline__ void fft128_block16(float2* bufA, float2* bufB, const float2* tw) {
    radix8_group1<SIGN>(bufA, bufB, tw);
    __syncthreads();
    int tid = threadIdx.x;
    int fi = tid >> 4;
    int i  = tid & 15;
    const int tk = i & 8;                     // i & ~7
    float2* R = bufB + fi * LDF;
    float2 a[8], e[8];
#pragma unroll
    for (int k = 0; k < 8; k++) a[k] = R[SWZI(i + 16 * k)];
    __syncthreads();                          // all loads before in-place stores
    radix8_butterfly<SIGN>(a, e, tk, tw);
    const int Q = i + 7 * tk;
#pragma unroll
    for (int k = 0; k < 8; k++) {
        float2 o;
        o.x = __shfl_xor_sync(0xffffffffu, e[k].x, 8);
        o.y = __shfl_xor_sync(0xffffffffu, e[k].y, 8);
        float2 res = (i < 8) ? f2add(e[k], o) : f2sub(o, e[k]);
        R[Q + 8 * k] = res;
    }
    __syncthreads();
}

// ---------------- K1: forward row FFT with real-pair packing, fp16 output.
__global__ void __launch_bounds__(256) k1_rowfft(const float* __restrict__ x) {
    __shared__ float2 bufA[16 * LDF], bufB[16 * LDF];
    __shared__ float2 tw[64];
    init_tw(tw);
    int tid = threadIdx.x;
    int blk = blockIdx.x;
    int bc = blk >> 2;
    int h0 = (blk & 3) << 5;              // 32 rows
    const float* xp = x + (size_t)bc * NN * NN + (size_t)h0 * NN;
    for (int i = tid; i < 16 * NN; i += 256) {
        int p = i >> 7, w = i & 127;
        bufA[p * LDF + w] = make_float2(xp[(2 * p) * NN + w], xp[(2 * p + 1) * NN + w]);
    }
    __syncthreads();
    fft128_block16<-1>(bufA, bufB, tw);
    __half2* out = g_X1h + (size_t)bc * NH * NN;
    for (int i = tid; i < NH * 16; i += 256) {
        int p = i & 15, wp = i >> 4;
        float2 A = bufB[p * LDF + wp];
        float2 B = bufB[p * LDF + ((NN - wp) & 127)];
        __half2 X0 = __floats2half2_rn(0.5f * (A.x + B.x), 0.5f * (A.y - B.y));
        __half2 X1 = __floats2half2_rn(0.5f * (A.y + B.y), 0.5f * (B.x - A.x));
        *(uint2*)&out[(size_t)wp * NN + h0 + 2 * p] = make_uint2(h2u(X0), h2u(X1));
    }
}

// ---------------- K2: forward column FFT, scatter to freq-major [f][b][c], fp16 out
__global__ void __launch_bounds__(256) k2_colfft() {
    __shared__ float2 bufA[16 * LDF], bufB[16 * LDF];
    __shared__ float2 tw[64];
    init_tw(tw);
    int tid = threadIdx.x;
    int blk = blockIdx.x;
    int b   = blk / (NH * 4);
    int rem = blk % (NH * 4);
    int wp  = rem >> 2;
    int c0  = (rem & 3) << 4;
    for (int i = tid; i < 16 * NN; i += 256) {
        int h = i & 127, cl = i >> 7;
        bufA[cl * LDF + h] = __half22float2(
            g_X1h[((size_t)(b * NC + c0 + cl) * NH + wp) * NN + h]);
    }
    __syncthreads();
    fft128_block16<-1>(bufA, bufB, tw);
    for (int i = tid; i < 16 * NN; i += 256) {
        int cl = i & 15, h = i >> 4;
        float2 v = bufB[cl * LDF + h];
        g_Xfh[((size_t)(wp * NN + h)) * NBC + b * NC + c0 + cl] =
            __floats2half2_rn(v.x, v.y);
    }
}

// ---------------- KW: full-row mirror pairing + cp.async double-buffer pipeline.
#define KWO 4
#define LDW 132
__global__ void __launch_bounds__(256) kw_weff(const float* __restrict__ wr,
                                               const float* __restrict__ wi) {
    __shared__ __align__(16) float Sr[2][KWO][2][LDW];   // [buf][oc][row][w]
    __shared__ __align__(16) float Si[2][KWO][2][LDW];
    int tid = threadIdx.x;
    int blk = blockIdx.x;                 // c*65 + hp
    int c   = blk / NH;
    int hp  = blk % NH;
    int h   = hp;
    int h2  = (NN - h) & 127;
    int self = (h2 == h);                 // h = 0 or 64

    auto issue = [&](int o0, int buf) {
#pragma unroll
        for (int ii = 0; ii < 2; ii++) {
            int i   = tid + ii * 256;
            int q   = i & 31;
            int r   = (i >> 5) & 1;
            int oc  = (i >> 6) & 3;
            int arr = i >> 8;
            const float* src = (arr ? wi : wr) +
                (size_t)((o0 + oc) * NC + c) * (NN * NN) +
                (size_t)(r ? h2 : h) * NN + q * 4;
            float* dst = arr ? &Si[buf][oc][r][q * 4] : &Sr[buf][oc][r][q * 4];
            unsigned da = (unsigned)__cvta_generic_to_shared(dst);
            asm volatile("cp.async.ca.shared.global [%0], [%1], 16;"
                         :: "r"(da), "l"(src) : "memory");
        }
        asm volatile("cp.async.commit_group;" ::: "memory");
    };

    issue(0, 0);
    issue(KWO, 1);
    for (int ph = 0; ph < 16; ph++) {
        int o0  = ph * KWO;
        int buf = ph & 1;
        if (ph == 15) asm volatile("cp.async.wait_group 0;" ::: "memory");
        else          asm volatile("cp.async.wait_group 1;" ::: "memory");
        __syncthreads();
        for (int i = tid; i < KWO * 2 * NH; i += 256) {
            int oc   = i & 3;
            int orow = (i >> 2) & 1;
            int wp   = i >> 3;
            if (orow & self) continue;    // self-paired row: emit once
            int w2 = (NN - wp) & 127;
            int ro = orow, rm = orow ^ 1;
            float a = 0.5f * (Sr[buf][oc][ro][wp] + Sr[buf][oc][rm][w2]);
            float b = 0.5f * (Si[buf][oc][ro][wp] - Si[buf][oc][rm][w2]);
            int row_h = orow ? h2 : h;
            g_Wf[((size_t)(wp * NN + row_h)) * (NC * NO) + c * NO + o0 + oc] =
                __floats2half2_rn(a, b);
        }
        __syncthreads();
        if (ph + 2 < 16) issue(o0 + 2 * KWO, buf);
    }
}

// ---------------- K3: per-frequency complex GEMM via tensor cores, plane form.
// Yr = (Xr@Wr) - (Xi@Wi), Yi = (Xr@Wi) + (Xi@Wr); products exact, fp32 accum.
#define LDP 72   // plane row stride (halves): 144B rows (16B-aligned)
__global__ void __launch_bounds__(256) k3_contract() {
    __shared__ __align__(16) __half Xr_s[NB][LDP], Xi_s[NB][LDP];   // 9.2 KB
    __shared__ __align__(16) __half Wr_s[NC][LDP], Wi_s[NC][LDP];   // 18.4 KB
    int tid = threadIdx.x;
    int lane = tid & 31, warp = tid >> 5;
    int f = blockIdx.x;

    const uint4* __restrict__ Xg4 = (const uint4*)(g_Xfh + (size_t)f * NBC);
    for (int i = tid; i < 512; i += 256) {
        uint4 v = Xg4[i];
        int b = i >> 4, c0 = (i & 15) << 2;
        __half2* hv = (__half2*)&v;
        *(uint2*)&Xr_s[b][c0] = make_uint2(h2u(__lows2half2(hv[0], hv[1])),
                                           h2u(__lows2half2(hv[2], hv[3])));
        *(uint2*)&Xi_s[b][c0] = make_uint2(h2u(__highs2half2(hv[0], hv[1])),
                                           h2u(__highs2half2(hv[2], hv[3])));
    }
    const uint4* __restrict__ Wg4 = (const uint4*)(g_Wf + (size_t)f * (NC * NO));
    for (int i = tid; i < 1024; i += 256) {
        uint4 v = Wg4[i];
        int c = i >> 4, o0 = (i & 15) << 2;
        __half2* hv = (__half2*)&v;
        *(uint2*)&Wr_s[c][o0] = make_uint2(h2u(__lows2half2(hv[0], hv[1])),
                                           h2u(__lows2half2(hv[2], hv[3])));
        *(uint2*)&Wi_s[c][o0] = make_uint2(h2u(__highs2half2(hv[0], hv[1])),
                                           h2u(__highs2half2(hv[2], hv[3])));
    }
    __syncthreads();

    int ob = warp << 3;                   // 8 o's per warp
    float r1[2][4], r2[2][4], yi[2][4];
#pragma unroll
    for (int mt = 0; mt < 2; mt++)
#pragma unroll
        for (int r = 0; r < 4; r++) { r1[mt][r] = 0.f; r2[mt][r] = 0.f; yi[mt][r] = 0.f; }

#pragma unroll
    for (int k = 0; k < 4; k++) {
        unsigned axr[2][4], axi[2][4], bwr[2], bwi[2];
#pragma unroll
        for (int mt = 0; mt < 2; mt++) {
            unsigned addr = (unsigned)__cvta_generic_to_shared(
                &Xr_s[mt * 16 + (lane & 15)][k * 16 + 8 * (lane >> 4)]);
            asm volatile("ldmatrix.sync.aligned.m8n8.x4.shared.b16 {%0,%1,%2,%3}, [%4];"
                : "=r"(axr[mt][0]), "=r"(axr[mt][1]), "=r"(axr[mt][2]), "=r"(axr[mt][3])
                : "r"(addr));
            addr = (unsigned)__cvta_generic_to_shared(
                &Xi_s[mt * 16 + (lane & 15)][k * 16 + 8 * (lane >> 4)]);
            asm volatile("ldmatrix.sync.aligned.m8n8.x4.shared.b16 {%0,%1,%2,%3}, [%4];"
                : "=r"(axi[mt][0]), "=r"(axi[mt][1]), "=r"(axi[mt][2]), "=r"(axi[mt][3])
                : "r"(addr));
        }
        {
            unsigned addr = (unsigned)__cvta_generic_to_shared(
                &Wr_s[k * 16 + (lane & 15)][ob]);
            asm volatile("ldmatrix.sync.aligned.m8n8.x2.trans.shared.b16 {%0,%1}, [%2];"
                : "=r"(bwr[0]), "=r"(bwr[1]) : "r"(addr));
            addr = (unsigned)__cvta_generic_to_shared(
                &Wi_s[k * 16 + (lane & 15)][ob]);
            asm volatile("ldmatrix.sync.aligned.m8n8.x2.trans.shared.b16 {%0,%1}, [%2];"
                : "=r"(bwi[0]), "=r"(bwi[1]) : "r"(addr));
        }
#pragma unroll
        for (int mt = 0; mt < 2; mt++) {
            asm volatile("mma.sync.aligned.m16n8k16.row.col.f32.f16.f16.f32 "
                "{%0,%1,%2,%3}, {%4,%5,%6,%7}, {%8,%9}, {%0,%1,%2,%3};"
                : "+f"(r1[mt][0]), "+f"(r1[mt][1]), "+f"(r1[mt][2]), "+f"(r1[mt][3])
                : "r"(axr[mt][0]), "r"(axr[mt][1]), "r"(axr[mt][2]), "r"(axr[mt][3]),
                  "r"(bwr[0]), "r"(bwr[1]));
            asm volatile("mma.sync.aligned.m16n8k16.row.col.f32.f16.f16.f32 "
                "{%0,%1,%2,%3}, {%4,%5,%6,%7}, {%8,%9}, {%0,%1,%2,%3};"
                : "+f"(r2[mt][0]), "+f"(r2[mt][1]), "+f"(r2[mt][2]), "+f"(r2[mt][3])
                : "r"(axi[mt][0]), "r"(axi[mt][1]), "r"(axi[mt][2]), "r"(axi[mt][3]),
                  "r"(bwi[0]), "r"(bwi[1]));
            asm volatile("mma.sync.aligned.m16n8k16.row.col.f32.f16.f16.f32 "
                "{%0,%1,%2,%3}, {%4,%5,%6,%7}, {%8,%9}, {%0,%1,%2,%3};"
                : "+f"(yi[mt][0]), "+f"(yi[mt][1]), "+f"(yi[mt][2]), "+f"(yi[mt][3])
                : "r"(axr[mt][0]), "r"(axr[mt][1]), "r"(axr[mt][2]), "r"(axr[mt][3]),
                  "r"(bwi[0]), "r"(bwi[1]));
            asm volatile("mma.sync.aligned.m16n8k16.row.col.f32.f16.f16.f32 "
                "{%0,%1,%2,%3}, {%4,%5,%6,%7}, {%8,%9}, {%0,%1,%2,%3};"
                : "+f"(yi[mt][0]), "+f"(yi[mt][1]), "+f"(yi[mt][2]), "+f"(yi[mt][3])
                : "r"(axi[mt][0]), "r"(axi[mt][1]), "r"(axi[mt][2]), "r"(axi[mt][3]),
                  "r"(bwr[0]), "r"(bwr[1]));
        }
    }

    __half2* __restrict__ Ygh = g_Yfh + (size_t)f * (NB * NO);
    int g = lane >> 2, tig = lane & 3;
    int o0 = ob + (tig << 1);
#pragma unroll
    for (int mt = 0; mt < 2; mt++) {
        int br = mt * 16 + g;
        __half2 e0 = __floats2half2_rn(r1[mt][0] - r2[mt][0], yi[mt][0]);
        __half2 e1 = __floats2half2_rn(r1[mt][1] - r2[mt][1], yi[mt][1]);
        __half2 e2 = __floats2half2_rn(r1[mt][2] - r2[mt][2], yi[mt][2]);
        __half2 e3 = __floats2half2_rn(r1[mt][3] - r2[mt][3], yi[mt][3]);
        *(uint2*)&Ygh[br * NO + o0]       = make_uint2(h2u(e0), h2u(e1));
        *(uint2*)&Ygh[(br + 8) * NO + o0] = make_uint2(h2u(e2), h2u(e3));
    }
}

// ---------------- K4: inverse column FFT (along h), to [bo][h][wp] fp16 (padded)
__global__ void __launch_bounds__(256) k4_colifft() {
    __shared__ float2 bufA[16 * LDF], bufB[16 * LDF];
    __shared__ float2 tw[64];
    init_tw(tw);
    int tid = threadIdx.x;
    int blk = blockIdx.x;
    int bt = blk / 17;
    int wt = blk % 17;
    int bo0 = bt << 2;
    int wp0 = wt << 2;
    for (int i = tid; i < 4 * NN; i += 256) {          // 512 uint4 loads (4 bo each)
        int wl = i & 3, h = i >> 2;
        int wp = wp0 + wl;
        uint4 v = make_uint4(0u, 0u, 0u, 0u);
        if (wp < NH)
            v = *(const uint4*)&g_Yfh[((size_t)(wp * NN + h)) * NBO + bo0];
        const unsigned* vp = &v.x;
#pragma unroll
        for (int bl = 0; bl < 4; bl++) {
            __half2 hv = *(__half2*)&vp[bl];
            bufA[((wl << 2) + bl) * LDF + h] = __half22float2(hv);
        }
    }
    __syncthreads();
    fft128_block16<1>(bufA, bufB, tw);
    for (int i = tid; i < 16 * NN; i += 256) {
        int wl = i & 3, bl = (i >> 2) & 3, h = i >> 4;
        int wp = wp0 + wl;
        int fi = (wl << 2) + bl;
        if (wp < NH) {
            float2 v = bufB[fi * LDF + h];
            g_Ych[((size_t)(bo0 + bl) * NN + h) * NHP + wp] = __floats2half2_rn(v.x, v.y);
        }
    }
}

// ---------------- K5: inverse row FFT with real-pair packing + bias + relu
__global__ void __launch_bounds__(256) k5_rowifft(const float* __restrict__ bias,
                                                  float* __restrict__ out) {
    __shared__ float2 bufA[16 * LDF], bufB[16 * LDF];
    __shared__ float2 tw[64];
    init_tw(tw);
    int tid = threadIdx.x;
    int blk = blockIdx.x;
    int bo = blk >> 2;
    int h0 = (blk & 3) << 5;              // 32 rows = 16 pairs
    int o  = bo & 63;
    const __half2* Yrow = g_Ych + (size_t)bo * NN * NHP;
    for (int i = tid; i < 16 * NN; i += 256) {
        int p = i >> 7, w = i & 127;
        int wp = (w <= 64) ? w : (NN - w);
        float2 A0 = __half22float2(Yrow[(size_t)(h0 + 2 * p)     * NHP + wp]);
        float2 A1 = __half22float2(Yrow[(size_t)(h0 + 2 * p + 1) * NHP + wp]);
        if (w > 64) { A0.y = -A0.y; A1.y = -A1.y; }
        bufA[p * LDF + w] = make_float2(A0.x - A1.y, A0.y + A1.x);
    }
    __syncthreads();
    fft128_block16<1>(bufA, bufB, tw);
    float bv = bias[o];
    const float scale = 1.0f / 16384.0f;
    float* op = out + (size_t)bo * NN * NN;
    for (int i = tid; i < 16 * NN; i += 256) {
        int p = i >> 7, w = i & 127;
        float2 v = bufB[p * LDF + w];
        float v0 = v.x * scale + bv;
        float v1 = v.y * scale + bv;
        op[(size_t)(h0 + 2 * p)     * NN + w] = fmaxf(v0, 0.f);
        op[(size_t)(h0 + 2 * p + 1) * NN + w] = fmaxf(v1, 0.f);
    }
}

// ---------------- launch ----------------
extern "C" void kernel_launch(void* const* d_in, const int* in_sizes, int n_in,
                              void* d_out, int out_size) {
    const float* x    = (const float*)d_in[0];
    const float* wr   = (const float*)d_in[1];
    const float* wi   = (const float*)d_in[2];
    const float* bias = (const float*)d_in[3];
    float* out = (float*)d_out;

    k1_rowfft <<<NBC * 4, 256>>>(x);             // 8192 blocks
    kw_weff   <<<NC * NH, 256>>>(wr, wi);        // 4160 blocks
    k2_colfft <<<NB * NH * 4, 256>>>();          // 8320 blocks
    k3_contract<<<NFREQ, 256>>>();               // 8320 blocks
    k4_colifft<<<(NBO / 4) * 17, 256>>>();       // 8704 blocks
    k5_rowifft<<<NBO * 4, 256>>>(bias, out);     // 8192 blocks
}